// round 6
// baseline (speedup 1.0000x reference)
#include <cuda_runtime.h>
#include <math.h>

// ---------------- problem constants ----------------
#define MAXN 20000
#define MAXE 320000
#define MAXET (MAXN + MAXE)
#define NGR 32

// ---------------- device scratch (no allocs allowed) ----------------
__device__ float g_h768[MAXN * 768];
__device__ float g_T[(size_t)MAXN * 1024];
__device__ float g_G[(size_t)MAXN * 1024];
__device__ float g_x1[(size_t)MAXN * 1024];
__device__ float g_x2[(size_t)MAXN * 1024];
__device__ float g_x3[MAXN * 256];
__device__ float g_es[MAXN * 4];
__device__ float g_ed[MAXN * 4];
__device__ int   g_deg[MAXN];
__device__ int   g_off[MAXN + 1];
__device__ int   g_cur[MAXN];
__device__ int   g_csr[MAXET];
__device__ float g_psum[NGR * 256];
__device__ float g_pmax[NGR * 256];
__device__ int   g_pcnt[NGR];

// Device-side buffer table: kernel_launch stays pure kernel launches.
#define BUF_H768 0
#define BUF_T    1
#define BUF_G    2
#define BUF_X1   3
#define BUF_X2   4
#define BUF_X3   5
__device__ float* const g_fptr[6] = { g_h768, g_T, g_G, g_x1, g_x2, g_x3 };

// ---------------- helpers ----------------
__device__ __forceinline__ float atomicMaxF(float* addr, float value) {
    if (value >= 0.f)
        return __int_as_float(atomicMax((int*)addr, __float_as_int(value)));
    else
        return __uint_as_float(atomicMin((unsigned int*)addr, __float_as_uint(value)));
}

__device__ __forceinline__ unsigned f2tf32(float x) {
    unsigned r;
    asm("cvt.rna.tf32.f32 %0, %1;" : "=r"(r) : "f"(x));
    return r;
}

__device__ __forceinline__ void mma_tf32(float c[4], unsigned a0, unsigned a1, unsigned a2, unsigned a3,
                                         unsigned b0, unsigned b1) {
    asm volatile(
        "mma.sync.aligned.m16n8k8.row.col.f32.tf32.tf32.f32 "
        "{%0,%1,%2,%3}, {%4,%5,%6,%7}, {%8,%9}, {%0,%1,%2,%3};"
        : "+f"(c[0]), "+f"(c[1]), "+f"(c[2]), "+f"(c[3])
        : "r"(a0), "r"(a1), "r"(a2), "r"(a3), "r"(b0), "r"(b1));
}

// ---------------- CSR build ----------------
__global__ void k_zero_deg(int n) {
    int i = blockIdx.x * 256 + threadIdx.x;
    if (i < n) g_deg[i] = 0;
}

__global__ void k_count_deg(const int* __restrict__ ei, int E, int N) {
    int i = blockIdx.x * 256 + threadIdx.x;
    if (i >= E + N) return;
    int dst = (i < E) ? ei[E + i] : (i - E);
    atomicAdd(&g_deg[dst], 1);
}

__global__ void __launch_bounds__(1024) k_scan_deg(int n) {
    const int NT = 1024;
    int tid = threadIdx.x;
    int chunk = (n + NT - 1) / NT;
    int b0 = tid * chunk;
    int lsum = 0;
    for (int i = 0; i < chunk; i++) {
        int j = b0 + i;
        if (j < n) lsum += g_deg[j];
    }
    __shared__ int s[NT];
    s[tid] = lsum;
    __syncthreads();
    for (int o = 1; o < NT; o <<= 1) {
        int t = (tid >= o) ? s[tid - o] : 0;
        __syncthreads();
        s[tid] += t;
        __syncthreads();
    }
    int run = s[tid] - lsum;  // exclusive prefix
    for (int i = 0; i < chunk; i++) {
        int j = b0 + i;
        if (j < n) { g_off[j] = run; g_cur[j] = run; run += g_deg[j]; }
    }
    if (tid == NT - 1) g_off[n] = s[NT - 1];
}

__global__ void k_scatter_edges(const int* __restrict__ ei, int E, int N) {
    int i = blockIdx.x * 256 + threadIdx.x;
    if (i >= E + N) return;
    int src, dst;
    if (i < E) { src = ei[i]; dst = ei[E + i]; }
    else       { src = i - E; dst = i - E; }
    int pos = atomicAdd(&g_cur[dst], 1);
    g_csr[pos] = src;
}

// ---------------- Tensor-core GEMM (3xTF32): C = act(A @ W + bias) ----------------
// Block tile 128x128x32, 8 warps (2x4), warp tile 64x32 via m16n8k8.
// A:[M,K] row-major, W:[K,N] row-major. K % 32 == 0, N % 128 == 0.
#define GM 128
#define GN 128
#define GKT 32
template <int ACT>
__global__ void __launch_bounds__(256) k_tgemm(const float* __restrict__ Aext, int a_id,
                                               const float* __restrict__ W,
                                               const float* __restrict__ bias, int c_id,
                                               int M, int N, int K) {
    const float* __restrict__ A = Aext ? Aext : g_fptr[a_id];
    float* __restrict__ C = g_fptr[c_id];

    __shared__ unsigned Ah[GM][GKT + 4];   // stride 36: banks (4r+c) conflict-free
    __shared__ unsigned Al[GM][GKT + 4];
    __shared__ unsigned Wh[GKT][GN + 8];   // stride 136: banks (8c+r) conflict-free
    __shared__ unsigned Wl[GKT][GN + 8];

    int tid = threadIdx.x, wid = tid >> 5, lane = tid & 31;
    int warp_m = wid & 1, warp_n = wid >> 1;   // 2 x 4 warps
    int row0 = blockIdx.y * GM, col0 = blockIdx.x * GN;
    int qr = lane >> 2, qc = lane & 3;         // quad row / col

    float acc[4][4][4] = {};

    for (int k0 = 0; k0 < K; k0 += GKT) {
        // Cooperative load+split: A tile (128x32) and W tile (32x128), 4 float4 each per thread
#pragma unroll
        for (int i = 0; i < 4; i++) {
            int p = tid * 4 + i;               // 0..1023
            {
                int ar = p >> 3, ak = (p & 7) * 4;
                float4 v = make_float4(0.f, 0.f, 0.f, 0.f);
                int gr = row0 + ar;
                if (gr < M) v = *(const float4*)(A + (size_t)gr * K + k0 + ak);
                unsigned h0 = f2tf32(v.x), h1 = f2tf32(v.y), h2 = f2tf32(v.z), h3 = f2tf32(v.w);
                Ah[ar][ak + 0] = h0; Al[ar][ak + 0] = f2tf32(v.x - __uint_as_float(h0));
                Ah[ar][ak + 1] = h1; Al[ar][ak + 1] = f2tf32(v.y - __uint_as_float(h1));
                Ah[ar][ak + 2] = h2; Al[ar][ak + 2] = f2tf32(v.z - __uint_as_float(h2));
                Ah[ar][ak + 3] = h3; Al[ar][ak + 3] = f2tf32(v.w - __uint_as_float(h3));
            }
            {
                int wr = p >> 5, wc = (p & 31) * 4;
                float4 v = *(const float4*)(W + (size_t)(k0 + wr) * N + col0 + wc);
                unsigned h0 = f2tf32(v.x), h1 = f2tf32(v.y), h2 = f2tf32(v.z), h3 = f2tf32(v.w);
                Wh[wr][wc + 0] = h0; Wl[wr][wc + 0] = f2tf32(v.x - __uint_as_float(h0));
                Wh[wr][wc + 1] = h1; Wl[wr][wc + 1] = f2tf32(v.y - __uint_as_float(h1));
                Wh[wr][wc + 2] = h2; Wl[wr][wc + 2] = f2tf32(v.z - __uint_as_float(h2));
                Wh[wr][wc + 3] = h3; Wl[wr][wc + 3] = f2tf32(v.w - __uint_as_float(h3));
            }
        }
        __syncthreads();

#pragma unroll
        for (int kk = 0; kk < 4; kk++) {
            int kb = kk * 8;
            unsigned ah[4][4], al[4][4];
#pragma unroll
            for (int i = 0; i < 4; i++) {
                int r = warp_m * 64 + i * 16;
                ah[i][0] = Ah[r + qr][kb + qc];
                ah[i][1] = Ah[r + qr + 8][kb + qc];
                ah[i][2] = Ah[r + qr][kb + qc + 4];
                ah[i][3] = Ah[r + qr + 8][kb + qc + 4];
                al[i][0] = Al[r + qr][kb + qc];
                al[i][1] = Al[r + qr + 8][kb + qc];
                al[i][2] = Al[r + qr][kb + qc + 4];
                al[i][3] = Al[r + qr + 8][kb + qc + 4];
            }
            unsigned bh[4][2], bl[4][2];
#pragma unroll
            for (int j = 0; j < 4; j++) {
                int c = warp_n * 32 + j * 8 + qr;
                bh[j][0] = Wh[kb + qc][c];
                bh[j][1] = Wh[kb + qc + 4][c];
                bl[j][0] = Wl[kb + qc][c];
                bl[j][1] = Wl[kb + qc + 4][c];
            }
#pragma unroll
            for (int i = 0; i < 4; i++)
#pragma unroll
                for (int j = 0; j < 4; j++) {
                    mma_tf32(acc[i][j], ah[i][0], ah[i][1], ah[i][2], ah[i][3], bh[j][0], bh[j][1]);
                    mma_tf32(acc[i][j], al[i][0], al[i][1], al[i][2], al[i][3], bh[j][0], bh[j][1]);
                    mma_tf32(acc[i][j], ah[i][0], ah[i][1], ah[i][2], ah[i][3], bl[j][0], bl[j][1]);
                }
        }
        __syncthreads();
    }

    // Epilogue: C frag (m16n8 f32): c0,c1 @ (qr, 2*qc), (qr, 2*qc+1); c2,c3 @ row+8
#pragma unroll
    for (int i = 0; i < 4; i++) {
#pragma unroll
        for (int j = 0; j < 4; j++) {
            int rg = row0 + warp_m * 64 + i * 16 + qr;
            int cg = col0 + warp_n * 32 + j * 8 + qc * 2;
            float b0v = 0.f, b1v = 0.f;
            if (bias) { b0v = bias[cg]; b1v = bias[cg + 1]; }
#pragma unroll
            for (int half = 0; half < 2; half++) {
                int r = rg + half * 8;
                if (r >= M) continue;
                float vx = acc[i][j][half * 2 + 0] + b0v;
                float vy = acc[i][j][half * 2 + 1] + b1v;
                if (ACT == 1) {
                    vx = vx > 0.f ? vx : (expf(vx) - 1.0f);
                    vy = vy > 0.f ? vy : (expf(vy) - 1.0f);
                }
                float2 v2 = make_float2(vx, vy);
                *(float2*)(C + (size_t)r * N + cg) = v2;
            }
        }
    }
}

// ---------------- attention dot products ----------------
__global__ void k_att_dots(const float* __restrict__ as_, const float* __restrict__ ad_,
                           int NH, int H, int C) {
    const float* __restrict__ T = g_T;
    int gw = (blockIdx.x * blockDim.x + threadIdx.x) >> 5;
    int lane = threadIdx.x & 31;
    if (gw >= NH) return;
    int n = gw / H, h = gw - n * H;
    const float* row = T + (size_t)n * H * C + (size_t)h * C;
    float a = 0.f, d = 0.f;
    for (int c = lane; c < C; c += 32) {
        float v = row[c];
        a += v * as_[h * C + c];
        d += v * ad_[h * C + c];
    }
    for (int o = 16; o; o >>= 1) {
        a += __shfl_xor_sync(0xffffffffu, a, o);
        d += __shfl_xor_sync(0xffffffffu, d, o);
    }
    if (lane == 0) { g_es[gw] = a; g_ed[gw] = d; }
}

// ---------------- GAT aggregation (per-dst-node softmax + weighted gather) ----------------
template <int H, int CPT>
__global__ void __launch_bounds__(256) k_gat_agg(const float* __restrict__ bias) {
    const int F = 256 * CPT;  // = H*256
    const float* __restrict__ T = g_T;
    const float* __restrict__ es = g_es;
    float* __restrict__ out = g_G;
    int node = blockIdx.x;
    int tid = threadIdx.x;
    int lane = tid & 31, wid = tid >> 5;
    int beg = g_off[node], end = g_off[node + 1];

    float edv[H];
#pragma unroll
    for (int h = 0; h < H; h++) edv[h] = g_ed[node * H + h];

    __shared__ float s_red[8][H];
    __shared__ float s_hmax[H];
    __shared__ float s_hden[H];

    // pass 1: per-head max logit
    float lmax[H];
#pragma unroll
    for (int h = 0; h < H; h++) lmax[h] = -INFINITY;
    for (int e = beg + tid; e < end; e += 256) {
        int s = g_csr[e];
        if (H == 4) {
            float4 e4 = *(const float4*)(es + s * 4);
            float l0 = e4.x + edv[0]; l0 = l0 > 0.f ? l0 : 0.2f * l0; lmax[0] = fmaxf(lmax[0], l0);
            float l1 = e4.y + edv[1]; l1 = l1 > 0.f ? l1 : 0.2f * l1; lmax[1] = fmaxf(lmax[1], l1);
            float l2 = e4.z + edv[2]; l2 = l2 > 0.f ? l2 : 0.2f * l2; lmax[2] = fmaxf(lmax[2], l2);
            float l3 = e4.w + edv[3]; l3 = l3 > 0.f ? l3 : 0.2f * l3; lmax[3] = fmaxf(lmax[3], l3);
        } else {
            float l = es[s * H] + edv[0];
            l = l > 0.f ? l : 0.2f * l;
            lmax[0] = fmaxf(lmax[0], l);
        }
    }
#pragma unroll
    for (int h = 0; h < H; h++)
        for (int o = 16; o; o >>= 1) lmax[h] = fmaxf(lmax[h], __shfl_xor_sync(0xffffffffu, lmax[h], o));
    if (lane == 0) {
#pragma unroll
        for (int h = 0; h < H; h++) s_red[wid][h] = lmax[h];
    }
    __syncthreads();
    if (tid == 0) {
#pragma unroll
        for (int h = 0; h < H; h++) {
            float m = s_red[0][h];
            for (int w = 1; w < 8; w++) m = fmaxf(m, s_red[w][h]);
            s_hmax[h] = m;
        }
    }
    __syncthreads();

    // pass 2: denominator
    float lden[H] = {};
    for (int e = beg + tid; e < end; e += 256) {
        int s = g_csr[e];
        if (H == 4) {
            float4 e4 = *(const float4*)(es + s * 4);
            float l0 = e4.x + edv[0]; l0 = l0 > 0.f ? l0 : 0.2f * l0; lden[0] += expf(l0 - s_hmax[0]);
            float l1 = e4.y + edv[1]; l1 = l1 > 0.f ? l1 : 0.2f * l1; lden[1] += expf(l1 - s_hmax[1]);
            float l2 = e4.z + edv[2]; l2 = l2 > 0.f ? l2 : 0.2f * l2; lden[2] += expf(l2 - s_hmax[2]);
            float l3 = e4.w + edv[3]; l3 = l3 > 0.f ? l3 : 0.2f * l3; lden[3] += expf(l3 - s_hmax[3]);
        } else {
            float l = es[s * H] + edv[0];
            l = l > 0.f ? l : 0.2f * l;
            lden[0] += expf(l - s_hmax[0]);
        }
    }
#pragma unroll
    for (int h = 0; h < H; h++)
        for (int o = 16; o; o >>= 1) lden[h] += __shfl_xor_sync(0xffffffffu, lden[h], o);
    if (lane == 0) {
#pragma unroll
        for (int h = 0; h < H; h++) s_red[wid][h] = lden[h];
    }
    __syncthreads();
    if (tid == 0) {
#pragma unroll
        for (int h = 0; h < H; h++) {
            float m = 0.f;
            for (int w = 0; w < 8; w++) m += s_red[w][h];
            s_hden[h] = m;
        }
    }
    __syncthreads();

    // pass 3: weighted gather
    float acc[CPT] = {};
    __shared__ int s_src[256];
    __shared__ float s_alpha[256 * H];
    for (int cb = beg; cb < end; cb += 256) {
        int cn = min(256, end - cb);
        if (tid < cn) {
            int s = g_csr[cb + tid];
            s_src[tid] = s;
#pragma unroll
            for (int h = 0; h < H; h++) {
                float l = es[s * H + h] + edv[h];
                l = l > 0.f ? l : 0.2f * l;
                s_alpha[tid * H + h] = expf(l - s_hmax[h]) / (s_hden[h] + 1e-16f);
            }
        }
        __syncthreads();
        if (CPT == 4) {
            const int head = tid >> 6;
            for (int j = 0; j < cn; j++) {
                int s = s_src[j];
                float alpha = s_alpha[j * H + head];
                float4 v = *(const float4*)(T + (size_t)s * F + tid * 4);
                acc[0] += alpha * v.x;
                acc[1] += alpha * v.y;
                acc[2] += alpha * v.z;
                acc[3] += alpha * v.w;
            }
        } else {
            for (int j = 0; j < cn; j++) {
                int s = s_src[j];
                float alpha = s_alpha[j * H];
                acc[0] += alpha * T[(size_t)s * F + tid];
            }
        }
        __syncthreads();
    }
#pragma unroll
    for (int q = 0; q < CPT; q++) {
        int c = tid * CPT + q;
        out[(size_t)node * F + c] = acc[q] + bias[c];
    }
}

// ---------------- LayerNorm + ELU (+ optional residual added AFTER elu) ----------------
__global__ void __launch_bounds__(256) k_ln_elu(const float* __restrict__ g,
                                                const float* __restrict__ b,
                                                int res_id, int out_id, int F) {
    const float* __restrict__ in = g_G;
    const float* __restrict__ res = (res_id >= 0) ? g_fptr[res_id] : nullptr;
    float* __restrict__ out = g_fptr[out_id];
    int node = blockIdx.x, tid = threadIdx.x;
    const float* row = in + (size_t)node * F;
    int nv = F >> 2;
    float s = 0.f, s2 = 0.f;
    for (int q = tid; q < nv; q += 256) {
        float4 v = *(const float4*)(row + q * 4);
        s += v.x + v.y + v.z + v.w;
        s2 += v.x * v.x + v.y * v.y + v.z * v.z + v.w * v.w;
    }
    __shared__ float sh[8], sh2[8];
    for (int o = 16; o; o >>= 1) {
        s += __shfl_xor_sync(0xffffffffu, s, o);
        s2 += __shfl_xor_sync(0xffffffffu, s2, o);
    }
    if ((tid & 31) == 0) { sh[tid >> 5] = s; sh2[tid >> 5] = s2; }
    __syncthreads();
    __shared__ float smean, sinv;
    if (tid == 0) {
        float ts = 0.f, t2 = 0.f;
        for (int w = 0; w < 8; w++) { ts += sh[w]; t2 += sh2[w]; }
        float mean = ts / F;
        float var = t2 / F - mean * mean;
        if (var < 0.f) var = 0.f;
        smean = mean;
        sinv = rsqrtf(var + 1e-5f);
    }
    __syncthreads();
    float mean = smean, inv = sinv;
    for (int q = tid; q < nv; q += 256) {
        int c = q * 4;
        float4 v = *(const float4*)(row + c);
        float4 gg = *(const float4*)(g + c);
        float4 bb = *(const float4*)(b + c);
        v.x = (v.x - mean) * inv * gg.x + bb.x;
        v.y = (v.y - mean) * inv * gg.y + bb.y;
        v.z = (v.z - mean) * inv * gg.z + bb.z;
        v.w = (v.w - mean) * inv * gg.w + bb.w;
        v.x = v.x > 0.f ? v.x : (expf(v.x) - 1.0f);
        v.y = v.y > 0.f ? v.y : (expf(v.y) - 1.0f);
        v.z = v.z > 0.f ? v.z : (expf(v.z) - 1.0f);
        v.w = v.w > 0.f ? v.w : (expf(v.w) - 1.0f);
        if (res) {
            float4 rr = *(const float4*)(res + (size_t)node * F + c);
            v.x += rr.x; v.y += rr.y; v.z += rr.z; v.w += rr.w;
        }
        *(float4*)(out + (size_t)node * F + c) = v;
    }
}

// ---------------- pooling ----------------
__global__ void k_pool_init() {
    int i = blockIdx.x * 256 + threadIdx.x;
    if (i < NGR * 256) { g_psum[i] = 0.f; g_pmax[i] = -INFINITY; }
    if (i < NGR) g_pcnt[i] = 0;
}

__global__ void k_pool_scatter(const int* __restrict__ batch, int N) {
    int i = blockIdx.x * 256 + threadIdx.x;
    if (i >= N * 256) return;
    int n = i >> 8, c = i & 255;
    int gph = batch[n];
    float v = g_x3[(size_t)n * 256 + c];
    atomicAdd(&g_psum[gph * 256 + c], v);
    atomicMaxF(&g_pmax[gph * 256 + c], v);
    if (c == 0) atomicAdd(&g_pcnt[gph], 1);
}

// ---------------- classifier head ----------------
__global__ void __launch_bounds__(128) k_classify(const float* __restrict__ w1, const float* __restrict__ b1,
                                                  const float* __restrict__ w2, const float* __restrict__ b2,
                                                  float* __restrict__ out) {
    int gph = blockIdx.x, tid = threadIdx.x;
    __shared__ float p[768];
    float cnt = (float)max(g_pcnt[gph], 1);
    for (int j = tid; j < 256; j += 128) {
        float sm = g_psum[gph * 256 + j];
        p[j] = sm / cnt;
        p[256 + j] = g_pmax[gph * 256 + j];
        p[512 + j] = sm;
    }
    __syncthreads();
    float h = b1[tid];
    for (int j = 0; j < 768; j++) h += p[j] * w1[j * 128 + tid];
    h = h > 0.f ? h : 0.f;
    float part = h * w2[tid];
    for (int o = 16; o; o >>= 1) part += __shfl_xor_sync(0xffffffffu, part, o);
    __shared__ float sr[4];
    if ((tid & 31) == 0) sr[tid >> 5] = part;
    __syncthreads();
    if (tid == 0) out[gph] = sr[0] + sr[1] + sr[2] + sr[3] + b2[0];
}

// ---------------- launch (pure kernel launches; graph-capture safe) ----------------
extern "C" void kernel_launch(void* const* d_in, const int* in_sizes, int n_in,
                              void* d_out, int out_size) {
    const float* x = (const float*)d_in[0];
    const int* ei = (const int*)d_in[1];
    const int* batch = (const int*)d_in[2];
    const float* proj_w = (const float*)d_in[3];
    const float* proj_b = (const float*)d_in[4];
    const float* gat1_w = (const float*)d_in[5];
    const float* att1_src = (const float*)d_in[6];
    const float* att1_dst = (const float*)d_in[7];
    const float* gat1_b = (const float*)d_in[8];
    const float* ln1_g = (const float*)d_in[9];
    const float* ln1_b = (const float*)d_in[10];
    const float* gat2_w = (const float*)d_in[11];
    const float* att2_src = (const float*)d_in[12];
    const float* att2_dst = (const float*)d_in[13];
    const float* gat2_b = (const float*)d_in[14];
    const float* ln2_g = (const float*)d_in[15];
    const float* ln2_b = (const float*)d_in[16];
    const float* gat3_w = (const float*)d_in[17];
    const float* att3_src = (const float*)d_in[18];
    const float* att3_dst = (const float*)d_in[19];
    const float* gat3_b = (const float*)d_in[20];
    const float* ln3_g = (const float*)d_in[21];
    const float* ln3_b = (const float*)d_in[22];
    const float* cls1_w = (const float*)d_in[23];
    const float* cls1_b = (const float*)d_in[24];
    const float* cls2_w = (const float*)d_in[25];
    const float* cls2_b = (const float*)d_in[26];
    float* out = (float*)d_out;

    int N = in_sizes[0] / 768;
    int E = in_sizes[1] / 2;
    int ET = E + N;

    // ---- CSR build (dst-grouped incoming edges incl. self-loops) ----
    k_zero_deg<<<(N + 255) / 256, 256>>>(N);
    k_count_deg<<<(ET + 255) / 256, 256>>>(ei, E, N);
    k_scan_deg<<<1, 1024>>>(N);
    k_scatter_edges<<<(ET + 255) / 256, 256>>>(ei, E, N);

    dim3 thr(256);
    int mgrid = (N + GM - 1) / GM;

    // ---- h = elu(x @ proj_w + proj_b) ----
    k_tgemm<1><<<dim3(768 / GN, mgrid), thr>>>(x, 0, proj_w, proj_b, BUF_H768, N, 768, 768);

    // ---- GAT layer 1: 768 -> 4x256 concat ----
    k_tgemm<0><<<dim3(1024 / GN, mgrid), thr>>>(nullptr, BUF_H768, gat1_w, nullptr, BUF_T, N, 1024, 768);
    k_att_dots<<<(N * 4 * 32 + 255) / 256, 256>>>(att1_src, att1_dst, N * 4, 4, 256);
    k_gat_agg<4, 4><<<N, 256>>>(gat1_b);
    k_ln_elu<<<N, 256>>>(ln1_g, ln1_b, -1, BUF_X1, 1024);

    // ---- GAT layer 2: 1024 -> 4x256 concat, residual ----
    k_tgemm<0><<<dim3(1024 / GN, mgrid), thr>>>(nullptr, BUF_X1, gat2_w, nullptr, BUF_T, N, 1024, 1024);
    k_att_dots<<<(N * 4 * 32 + 255) / 256, 256>>>(att2_src, att2_dst, N * 4, 4, 256);
    k_gat_agg<4, 4><<<N, 256>>>(gat2_b);
    k_ln_elu<<<N, 256>>>(ln2_g, ln2_b, BUF_X1, BUF_X2, 1024);

    // ---- GAT layer 3: 1024 -> 1x256 (mean over 1 head = identity) ----
    k_tgemm<0><<<dim3(256 / GN, mgrid), thr>>>(nullptr, BUF_X2, gat3_w, nullptr, BUF_T, N, 256, 1024);
    k_att_dots<<<(N * 1 * 32 + 255) / 256, 256>>>(att3_src, att3_dst, N * 1, 1, 256);
    k_gat_agg<1, 1><<<N, 256>>>(gat3_b);
    k_ln_elu<<<N, 256>>>(ln3_g, ln3_b, -1, BUF_X3, 256);

    // ---- pooling + classifier ----
    k_pool_init<<<(NGR * 256 + 255) / 256, 256>>>();
    k_pool_scatter<<<(N * 256 + 255) / 256, 256>>>(batch, N);
    k_classify<<<NGR, 128>>>(cls1_w, cls1_b, cls2_w, cls2_b, out);
}

// round 8
// speedup vs baseline: 1.2625x; 1.2625x over previous
#include <cuda_runtime.h>
#include <cuda_bf16.h>
#include <math.h>

// ---------------- problem constants ----------------
#define MAXN 20000
#define MAXE 320000
#define MAXET (MAXN + MAXE)
#define NGR 32

// ---------------- device scratch (no allocs allowed) ----------------
__device__ float g_h768[MAXN * 768];
__device__ float g_T[(size_t)MAXN * 1024];
__device__ float g_G[(size_t)MAXN * 1024];
__device__ float g_x1[(size_t)MAXN * 1024];
__device__ float g_x2[(size_t)MAXN * 1024];
__device__ float g_x3[MAXN * 256];
__device__ float g_es[MAXN * 4];
__device__ float g_ed[MAXN * 4];
__device__ int   g_deg[MAXN];
__device__ int   g_off[MAXN + 1];
__device__ int   g_cur[MAXN];
__device__ int   g_csr[MAXET];
__device__ float g_psum[NGR * 256];
__device__ float g_pmax[NGR * 256];
__device__ int   g_pcnt[NGR];

// Device-side buffer table: kernel_launch stays pure kernel launches.
#define BUF_H768 0
#define BUF_T    1
#define BUF_G    2
#define BUF_X1   3
#define BUF_X2   4
#define BUF_X3   5
__device__ float* const g_fptr[6] = { g_h768, g_T, g_G, g_x1, g_x2, g_x3 };

// ---------------- helpers ----------------
__device__ __forceinline__ float atomicMaxF(float* addr, float value) {
    if (value >= 0.f)
        return __int_as_float(atomicMax((int*)addr, __float_as_int(value)));
    else
        return __uint_as_float(atomicMin((unsigned int*)addr, __float_as_uint(value)));
}

// Split x into bf16 hi + bf16 lo (residual). Returns packed pair helpers below.
__device__ __forceinline__ void bf_split(float x, unsigned short& hi, unsigned short& lo) {
    __nv_bfloat16 h = __float2bfloat16_rn(x);
    float hf = __bfloat162float(h);
    __nv_bfloat16 l = __float2bfloat16_rn(x - hf);
    hi = __bfloat16_as_ushort(h);
    lo = __bfloat16_as_ushort(l);
}

__device__ __forceinline__ void mma_bf16(float c[4], unsigned a0, unsigned a1, unsigned a2, unsigned a3,
                                         unsigned b0, unsigned b1) {
    asm volatile(
        "mma.sync.aligned.m16n8k16.row.col.f32.bf16.bf16.f32 "
        "{%0,%1,%2,%3}, {%4,%5,%6,%7}, {%8,%9}, {%0,%1,%2,%3};"
        : "+f"(c[0]), "+f"(c[1]), "+f"(c[2]), "+f"(c[3])
        : "r"(a0), "r"(a1), "r"(a2), "r"(a3), "r"(b0), "r"(b1));
}

// ---------------- CSR build ----------------
__global__ void k_zero_deg(int n) {
    int i = blockIdx.x * 256 + threadIdx.x;
    if (i < n) g_deg[i] = 0;
}

__global__ void k_count_deg(const int* __restrict__ ei, int E, int N) {
    int i = blockIdx.x * 256 + threadIdx.x;
    if (i >= E + N) return;
    int dst = (i < E) ? ei[E + i] : (i - E);
    atomicAdd(&g_deg[dst], 1);
}

__global__ void __launch_bounds__(1024) k_scan_deg(int n) {
    const int NT = 1024;
    int tid = threadIdx.x;
    int chunk = (n + NT - 1) / NT;
    int b0 = tid * chunk;
    int lsum = 0;
    for (int i = 0; i < chunk; i++) {
        int j = b0 + i;
        if (j < n) lsum += g_deg[j];
    }
    __shared__ int s[NT];
    s[tid] = lsum;
    __syncthreads();
    for (int o = 1; o < NT; o <<= 1) {
        int t = (tid >= o) ? s[tid - o] : 0;
        __syncthreads();
        s[tid] += t;
        __syncthreads();
    }
    int run = s[tid] - lsum;  // exclusive prefix
    for (int i = 0; i < chunk; i++) {
        int j = b0 + i;
        if (j < n) { g_off[j] = run; g_cur[j] = run; run += g_deg[j]; }
    }
    if (tid == NT - 1) g_off[n] = s[NT - 1];
}

__global__ void k_scatter_edges(const int* __restrict__ ei, int E, int N) {
    int i = blockIdx.x * 256 + threadIdx.x;
    if (i >= E + N) return;
    int src, dst;
    if (i < E) { src = ei[i]; dst = ei[E + i]; }
    else       { src = i - E; dst = i - E; }
    int pos = atomicAdd(&g_cur[dst], 1);
    g_csr[pos] = src;
}

// ---------------- Tensor-core GEMM (bf16 hi/lo split, 3 terms): C = act(A @ W + bias) ----
// Block tile 128x128x32, 8 warps (2x4), warp tile 64x32 via m16n8k16.bf16.
// A:[M,K] row-major, W:[K,N] row-major. K % 32 == 0, N % 128 == 0.
#define GM 128
#define GN 128
#define GKT 32
#define SLD 20   // smem row stride (uint32) - conflict-free for fragment reads
template <int ACT>
__global__ void __launch_bounds__(256) k_tgemm(const float* __restrict__ Aext, int a_id,
                                               const float* __restrict__ W,
                                               const float* __restrict__ bias, int c_id,
                                               int M, int N, int K) {
    const float* __restrict__ A = Aext ? Aext : g_fptr[a_id];
    float* __restrict__ C = g_fptr[c_id];

    // packed bf16x2 tiles: A rows x kpairs, W cols x kpairs
    __shared__ unsigned A2h[GM][SLD];
    __shared__ unsigned A2l[GM][SLD];
    __shared__ unsigned Wph[GN][SLD];
    __shared__ unsigned Wpl[GN][SLD];

    int tid = threadIdx.x, wid = tid >> 5, lane = tid & 31;
    int warp_m = wid & 1, warp_n = wid >> 1;   // 2 x 4 warps
    int row0 = blockIdx.y * GM, col0 = blockIdx.x * GN;
    int qr = lane >> 2, qc = lane & 3;         // quad row / col

    float acc[4][4][4] = {};

    for (int k0 = 0; k0 < K; k0 += GKT) {
        // ---- load + split A tile (128 rows x 32 k) ----
#pragma unroll
        for (int i = 0; i < 4; i++) {
            int u = tid * 4 + i;             // 0..1023
            int row = u >> 3, gkp = u & 7;   // gkp: group of 4 k (= 2 kpairs)
            float4 v = make_float4(0.f, 0.f, 0.f, 0.f);
            int gr = row0 + row;
            if (gr < M) v = *(const float4*)(A + (size_t)gr * K + k0 + gkp * 4);
            unsigned short h0, l0, h1, l1, h2, l2, h3, l3;
            bf_split(v.x, h0, l0); bf_split(v.y, h1, l1);
            bf_split(v.z, h2, l2); bf_split(v.w, h3, l3);
            A2h[row][gkp * 2 + 0] = (unsigned)h0 | ((unsigned)h1 << 16);
            A2h[row][gkp * 2 + 1] = (unsigned)h2 | ((unsigned)h3 << 16);
            A2l[row][gkp * 2 + 0] = (unsigned)l0 | ((unsigned)l1 << 16);
            A2l[row][gkp * 2 + 1] = (unsigned)l2 | ((unsigned)l3 << 16);
        }
        // ---- load + split W tile (32 k x 128 n), packed as [n][kpair] ----
#pragma unroll
        for (int uu = 0; uu < 2; uu++) {
            int u = tid + uu * 256;          // 0..511
            int r = u >> 5;                  // kpair 0..15
            int nc = (u & 31) * 4;           // n offset 0..124
            const float* wp = W + (size_t)(k0 + 2 * r) * N + col0 + nc;
            float4 va = *(const float4*)wp;        // k = 2r
            float4 vb = *(const float4*)(wp + N);  // k = 2r+1
            unsigned short ha, la, hb, lb;
            bf_split(va.x, ha, la); bf_split(vb.x, hb, lb);
            Wph[nc + 0][r] = (unsigned)ha | ((unsigned)hb << 16);
            Wpl[nc + 0][r] = (unsigned)la | ((unsigned)lb << 16);
            bf_split(va.y, ha, la); bf_split(vb.y, hb, lb);
            Wph[nc + 1][r] = (unsigned)ha | ((unsigned)hb << 16);
            Wpl[nc + 1][r] = (unsigned)la | ((unsigned)lb << 16);
            bf_split(va.z, ha, la); bf_split(vb.z, hb, lb);
            Wph[nc + 2][r] = (unsigned)ha | ((unsigned)hb << 16);
            Wpl[nc + 2][r] = (unsigned)la | ((unsigned)lb << 16);
            bf_split(va.w, ha, la); bf_split(vb.w, hb, lb);
            Wph[nc + 3][r] = (unsigned)ha | ((unsigned)hb << 16);
            Wpl[nc + 3][r] = (unsigned)la | ((unsigned)lb << 16);
        }
        __syncthreads();

        // ---- 2 x k16 steps ----
#pragma unroll
        for (int kk = 0; kk < 2; kk++) {
            int kb = kk * 8;  // kpair offset
            unsigned ah[4][4], al[4][4];
#pragma unroll
            for (int i = 0; i < 4; i++) {
                int r = warp_m * 64 + i * 16;
                ah[i][0] = A2h[r + qr][kb + qc];
                ah[i][1] = A2h[r + qr + 8][kb + qc];
                ah[i][2] = A2h[r + qr][kb + qc + 4];
                ah[i][3] = A2h[r + qr + 8][kb + qc + 4];
                al[i][0] = A2l[r + qr][kb + qc];
                al[i][1] = A2l[r + qr + 8][kb + qc];
                al[i][2] = A2l[r + qr][kb + qc + 4];
                al[i][3] = A2l[r + qr + 8][kb + qc + 4];
            }
            unsigned bh[4][2], bl[4][2];
#pragma unroll
            for (int j = 0; j < 4; j++) {
                int c = warp_n * 32 + j * 8 + qr;
                bh[j][0] = Wph[c][kb + qc];
                bh[j][1] = Wph[c][kb + qc + 4];
                bl[j][0] = Wpl[c][kb + qc];
                bl[j][1] = Wpl[c][kb + qc + 4];
            }
#pragma unroll
            for (int i = 0; i < 4; i++)
#pragma unroll
                for (int j = 0; j < 4; j++) {
                    mma_bf16(acc[i][j], ah[i][0], ah[i][1], ah[i][2], ah[i][3], bh[j][0], bh[j][1]);
                    mma_bf16(acc[i][j], al[i][0], al[i][1], al[i][2], al[i][3], bh[j][0], bh[j][1]);
                    mma_bf16(acc[i][j], ah[i][0], ah[i][1], ah[i][2], ah[i][3], bl[j][0], bl[j][1]);
                }
        }
        __syncthreads();
    }

    // Epilogue: C frag (m16n8 f32): c0,c1 @ (qr, 2*qc..+1); c2,c3 @ row+8
#pragma unroll
    for (int i = 0; i < 4; i++) {
#pragma unroll
        for (int j = 0; j < 4; j++) {
            int rg = row0 + warp_m * 64 + i * 16 + qr;
            int cg = col0 + warp_n * 32 + j * 8 + qc * 2;
            float b0v = 0.f, b1v = 0.f;
            if (bias) { b0v = bias[cg]; b1v = bias[cg + 1]; }
#pragma unroll
            for (int half = 0; half < 2; half++) {
                int r = rg + half * 8;
                if (r >= M) continue;
                float vx = acc[i][j][half * 2 + 0] + b0v;
                float vy = acc[i][j][half * 2 + 1] + b1v;
                if (ACT == 1) {
                    vx = vx > 0.f ? vx : (expf(vx) - 1.0f);
                    vy = vy > 0.f ? vy : (expf(vy) - 1.0f);
                }
                float2 v2 = make_float2(vx, vy);
                *(float2*)(C + (size_t)r * N + cg) = v2;
            }
        }
    }
}

// ---------------- attention dot products ----------------
__global__ void k_att_dots(const float* __restrict__ as_, const float* __restrict__ ad_,
                           int NH, int H, int C) {
    const float* __restrict__ T = g_T;
    int gw = (blockIdx.x * blockDim.x + threadIdx.x) >> 5;
    int lane = threadIdx.x & 31;
    if (gw >= NH) return;
    int n = gw / H, h = gw - n * H;
    const float* row = T + (size_t)n * H * C + (size_t)h * C;
    float a = 0.f, d = 0.f;
    for (int c = lane; c < C; c += 32) {
        float v = row[c];
        a += v * as_[h * C + c];
        d += v * ad_[h * C + c];
    }
    for (int o = 16; o; o >>= 1) {
        a += __shfl_xor_sync(0xffffffffu, a, o);
        d += __shfl_xor_sync(0xffffffffu, d, o);
    }
    if (lane == 0) { g_es[gw] = a; g_ed[gw] = d; }
}

// ---------------- GAT aggregation (per-dst-node softmax + weighted gather) ----------------
template <int H, int CPT>
__global__ void __launch_bounds__(256) k_gat_agg(const float* __restrict__ bias) {
    const int F = 256 * CPT;  // = H*256
    const float* __restrict__ T = g_T;
    const float* __restrict__ es = g_es;
    float* __restrict__ out = g_G;
    int node = blockIdx.x;
    int tid = threadIdx.x;
    int lane = tid & 31, wid = tid >> 5;
    int beg = g_off[node], end = g_off[node + 1];

    float edv[H];
#pragma unroll
    for (int h = 0; h < H; h++) edv[h] = g_ed[node * H + h];

    __shared__ float s_red[8][H];
    __shared__ float s_hmax[H];
    __shared__ float s_hden[H];

    // pass 1: per-head max logit
    float lmax[H];
#pragma unroll
    for (int h = 0; h < H; h++) lmax[h] = -INFINITY;
    for (int e = beg + tid; e < end; e += 256) {
        int s = g_csr[e];
        if (H == 4) {
            float4 e4 = *(const float4*)(es + s * 4);
            float l0 = e4.x + edv[0]; l0 = l0 > 0.f ? l0 : 0.2f * l0; lmax[0] = fmaxf(lmax[0], l0);
            float l1 = e4.y + edv[1]; l1 = l1 > 0.f ? l1 : 0.2f * l1; lmax[1] = fmaxf(lmax[1], l1);
            float l2 = e4.z + edv[2]; l2 = l2 > 0.f ? l2 : 0.2f * l2; lmax[2] = fmaxf(lmax[2], l2);
            float l3 = e4.w + edv[3]; l3 = l3 > 0.f ? l3 : 0.2f * l3; lmax[3] = fmaxf(lmax[3], l3);
        } else {
            float l = es[s * H] + edv[0];
            l = l > 0.f ? l : 0.2f * l;
            lmax[0] = fmaxf(lmax[0], l);
        }
    }
#pragma unroll
    for (int h = 0; h < H; h++)
        for (int o = 16; o; o >>= 1) lmax[h] = fmaxf(lmax[h], __shfl_xor_sync(0xffffffffu, lmax[h], o));
    if (lane == 0) {
#pragma unroll
        for (int h = 0; h < H; h++) s_red[wid][h] = lmax[h];
    }
    __syncthreads();
    if (tid == 0) {
#pragma unroll
        for (int h = 0; h < H; h++) {
            float m = s_red[0][h];
            for (int w = 1; w < 8; w++) m = fmaxf(m, s_red[w][h]);
            s_hmax[h] = m;
        }
    }
    __syncthreads();

    // pass 2: denominator
    float lden[H] = {};
    for (int e = beg + tid; e < end; e += 256) {
        int s = g_csr[e];
        if (H == 4) {
            float4 e4 = *(const float4*)(es + s * 4);
            float l0 = e4.x + edv[0]; l0 = l0 > 0.f ? l0 : 0.2f * l0; lden[0] += expf(l0 - s_hmax[0]);
            float l1 = e4.y + edv[1]; l1 = l1 > 0.f ? l1 : 0.2f * l1; lden[1] += expf(l1 - s_hmax[1]);
            float l2 = e4.z + edv[2]; l2 = l2 > 0.f ? l2 : 0.2f * l2; lden[2] += expf(l2 - s_hmax[2]);
            float l3 = e4.w + edv[3]; l3 = l3 > 0.f ? l3 : 0.2f * l3; lden[3] += expf(l3 - s_hmax[3]);
        } else {
            float l = es[s * H] + edv[0];
            l = l > 0.f ? l : 0.2f * l;
            lden[0] += expf(l - s_hmax[0]);
        }
    }
#pragma unroll
    for (int h = 0; h < H; h++)
        for (int o = 16; o; o >>= 1) lden[h] += __shfl_xor_sync(0xffffffffu, lden[h], o);
    if (lane == 0) {
#pragma unroll
        for (int h = 0; h < H; h++) s_red[wid][h] = lden[h];
    }
    __syncthreads();
    if (tid == 0) {
#pragma unroll
        for (int h = 0; h < H; h++) {
            float m = 0.f;
            for (int w = 0; w < 8; w++) m += s_red[w][h];
            s_hden[h] = m;
        }
    }
    __syncthreads();

    // pass 3: weighted gather
    float acc[CPT] = {};
    __shared__ int s_src[256];
    __shared__ float s_alpha[256 * H];
    for (int cb = beg; cb < end; cb += 256) {
        int cn = min(256, end - cb);
        if (tid < cn) {
            int s = g_csr[cb + tid];
            s_src[tid] = s;
#pragma unroll
            for (int h = 0; h < H; h++) {
                float l = es[s * H + h] + edv[h];
                l = l > 0.f ? l : 0.2f * l;
                s_alpha[tid * H + h] = expf(l - s_hmax[h]) / (s_hden[h] + 1e-16f);
            }
        }
        __syncthreads();
        if (CPT == 4) {
            const int head = tid >> 6;
            for (int j = 0; j < cn; j++) {
                int s = s_src[j];
                float alpha = s_alpha[j * H + head];
                float4 v = *(const float4*)(T + (size_t)s * F + tid * 4);
                acc[0] += alpha * v.x;
                acc[1] += alpha * v.y;
                acc[2] += alpha * v.z;
                acc[3] += alpha * v.w;
            }
        } else {
            for (int j = 0; j < cn; j++) {
                int s = s_src[j];
                float alpha = s_alpha[j * H];
                acc[0] += alpha * T[(size_t)s * F + tid];
            }
        }
        __syncthreads();
    }
#pragma unroll
    for (int q = 0; q < CPT; q++) {
        int c = tid * CPT + q;
        out[(size_t)node * F + c] = acc[q] + bias[c];
    }
}

// ---------------- LayerNorm + ELU (+ optional residual added AFTER elu) ----------------
__global__ void __launch_bounds__(256) k_ln_elu(const float* __restrict__ g,
                                                const float* __restrict__ b,
                                                int res_id, int out_id, int F) {
    const float* __restrict__ in = g_G;
    const float* __restrict__ res = (res_id >= 0) ? g_fptr[res_id] : nullptr;
    float* __restrict__ out = g_fptr[out_id];
    int node = blockIdx.x, tid = threadIdx.x;
    const float* row = in + (size_t)node * F;
    int nv = F >> 2;
    float s = 0.f, s2 = 0.f;
    for (int q = tid; q < nv; q += 256) {
        float4 v = *(const float4*)(row + q * 4);
        s += v.x + v.y + v.z + v.w;
        s2 += v.x * v.x + v.y * v.y + v.z * v.z + v.w * v.w;
    }
    __shared__ float sh[8], sh2[8];
    for (int o = 16; o; o >>= 1) {
        s += __shfl_xor_sync(0xffffffffu, s, o);
        s2 += __shfl_xor_sync(0xffffffffu, s2, o);
    }
    if ((tid & 31) == 0) { sh[tid >> 5] = s; sh2[tid >> 5] = s2; }
    __syncthreads();
    __shared__ float smean, sinv;
    if (tid == 0) {
        float ts = 0.f, t2 = 0.f;
        for (int w = 0; w < 8; w++) { ts += sh[w]; t2 += sh2[w]; }
        float mean = ts / F;
        float var = t2 / F - mean * mean;
        if (var < 0.f) var = 0.f;
        smean = mean;
        sinv = rsqrtf(var + 1e-5f);
    }
    __syncthreads();
    float mean = smean, inv = sinv;
    for (int q = tid; q < nv; q += 256) {
        int c = q * 4;
        float4 v = *(const float4*)(row + c);
        float4 gg = *(const float4*)(g + c);
        float4 bb = *(const float4*)(b + c);
        v.x = (v.x - mean) * inv * gg.x + bb.x;
        v.y = (v.y - mean) * inv * gg.y + bb.y;
        v.z = (v.z - mean) * inv * gg.z + bb.z;
        v.w = (v.w - mean) * inv * gg.w + bb.w;
        v.x = v.x > 0.f ? v.x : (expf(v.x) - 1.0f);
        v.y = v.y > 0.f ? v.y : (expf(v.y) - 1.0f);
        v.z = v.z > 0.f ? v.z : (expf(v.z) - 1.0f);
        v.w = v.w > 0.f ? v.w : (expf(v.w) - 1.0f);
        if (res) {
            float4 rr = *(const float4*)(res + (size_t)node * F + c);
            v.x += rr.x; v.y += rr.y; v.z += rr.z; v.w += rr.w;
        }
        *(float4*)(out + (size_t)node * F + c) = v;
    }
}

// ---------------- pooling ----------------
__global__ void k_pool_init() {
    int i = blockIdx.x * 256 + threadIdx.x;
    if (i < NGR * 256) { g_psum[i] = 0.f; g_pmax[i] = -INFINITY; }
    if (i < NGR) g_pcnt[i] = 0;
}

__global__ void k_pool_scatter(const int* __restrict__ batch, int N) {
    int i = blockIdx.x * 256 + threadIdx.x;
    if (i >= N * 256) return;
    int n = i >> 8, c = i & 255;
    int gph = batch[n];
    float v = g_x3[(size_t)n * 256 + c];
    atomicAdd(&g_psum[gph * 256 + c], v);
    atomicMaxF(&g_pmax[gph * 256 + c], v);
    if (c == 0) atomicAdd(&g_pcnt[gph], 1);
}

// ---------------- classifier head ----------------
__global__ void __launch_bounds__(128) k_classify(const float* __restrict__ w1, const float* __restrict__ b1,
                                                  const float* __restrict__ w2, const float* __restrict__ b2,
                                                  float* __restrict__ out) {
    int gph = blockIdx.x, tid = threadIdx.x;
    __shared__ float p[768];
    float cnt = (float)max(g_pcnt[gph], 1);
    for (int j = tid; j < 256; j += 128) {
        float sm = g_psum[gph * 256 + j];
        p[j] = sm / cnt;
        p[256 + j] = g_pmax[gph * 256 + j];
        p[512 + j] = sm;
    }
    __syncthreads();
    float h = b1[tid];
    for (int j = 0; j < 768; j++) h += p[j] * w1[j * 128 + tid];
    h = h > 0.f ? h : 0.f;
    float part = h * w2[tid];
    for (int o = 16; o; o >>= 1) part += __shfl_xor_sync(0xffffffffu, part, o);
    __shared__ float sr[4];
    if ((tid & 31) == 0) sr[tid >> 5] = part;
    __syncthreads();
    if (tid == 0) out[gph] = sr[0] + sr[1] + sr[2] + sr[3] + b2[0];
}

// ---------------- launch (pure kernel launches; graph-capture safe) ----------------
extern "C" void kernel_launch(void* const* d_in, const int* in_sizes, int n_in,
                              void* d_out, int out_size) {
    const float* x = (const float*)d_in[0];
    const int* ei = (const int*)d_in[1];
    const int* batch = (const int*)d_in[2];
    const float* proj_w = (const float*)d_in[3];
    const float* proj_b = (const float*)d_in[4];
    const float* gat1_w = (const float*)d_in[5];
    const float* att1_src = (const float*)d_in[6];
    const float* att1_dst = (const float*)d_in[7];
    const float* gat1_b = (const float*)d_in[8];
    const float* ln1_g = (const float*)d_in[9];
    const float* ln1_b = (const float*)d_in[10];
    const float* gat2_w = (const float*)d_in[11];
    const float* att2_src = (const float*)d_in[12];
    const float* att2_dst = (const float*)d_in[13];
    const float* gat2_b = (const float*)d_in[14];
    const float* ln2_g = (const float*)d_in[15];
    const float* ln2_b = (const float*)d_in[16];
    const float* gat3_w = (const float*)d_in[17];
    const float* att3_src = (const float*)d_in[18];
    const float* att3_dst = (const float*)d_in[19];
    const float* gat3_b = (const float*)d_in[20];
    const float* ln3_g = (const float*)d_in[21];
    const float* ln3_b = (const float*)d_in[22];
    const float* cls1_w = (const float*)d_in[23];
    const float* cls1_b = (const float*)d_in[24];
    const float* cls2_w = (const float*)d_in[25];
    const float* cls2_b = (const float*)d_in[26];
    float* out = (float*)d_out;

    int N = in_sizes[0] / 768;
    int E = in_sizes[1] / 2;
    int ET = E + N;

    // ---- CSR build (dst-grouped incoming edges incl. self-loops) ----
    k_zero_deg<<<(N + 255) / 256, 256>>>(N);
    k_count_deg<<<(ET + 255) / 256, 256>>>(ei, E, N);
    k_scan_deg<<<1, 1024>>>(N);
    k_scatter_edges<<<(ET + 255) / 256, 256>>>(ei, E, N);

    dim3 thr(256);
    int mgrid = (N + GM - 1) / GM;

    // ---- h = elu(x @ proj_w + proj_b) ----
    k_tgemm<1><<<dim3(768 / GN, mgrid), thr>>>(x, 0, proj_w, proj_b, BUF_H768, N, 768, 768);

    // ---- GAT layer 1: 768 -> 4x256 concat ----
    k_tgemm<0><<<dim3(1024 / GN, mgrid), thr>>>(nullptr, BUF_H768, gat1_w, nullptr, BUF_T, N, 1024, 768);
    k_att_dots<<<(N * 4 * 32 + 255) / 256, 256>>>(att1_src, att1_dst, N * 4, 4, 256);
    k_gat_agg<4, 4><<<N, 256>>>(gat1_b);
    k_ln_elu<<<N, 256>>>(ln1_g, ln1_b, -1, BUF_X1, 1024);

    // ---- GAT layer 2: 1024 -> 4x256 concat, residual ----
    k_tgemm<0><<<dim3(1024 / GN, mgrid), thr>>>(nullptr, BUF_X1, gat2_w, nullptr, BUF_T, N, 1024, 1024);
    k_att_dots<<<(N * 4 * 32 + 255) / 256, 256>>>(att2_src, att2_dst, N * 4, 4, 256);
    k_gat_agg<4, 4><<<N, 256>>>(gat2_b);
    k_ln_elu<<<N, 256>>>(ln2_g, ln2_b, BUF_X1, BUF_X2, 1024);

    // ---- GAT layer 3: 1024 -> 1x256 (mean over 1 head = identity) ----
    k_tgemm<0><<<dim3(256 / GN, mgrid), thr>>>(nullptr, BUF_X2, gat3_w, nullptr, BUF_T, N, 256, 1024);
    k_att_dots<<<(N * 1 * 32 + 255) / 256, 256>>>(att3_src, att3_dst, N * 1, 1, 256);
    k_gat_agg<1, 1><<<N, 256>>>(gat3_b);
    k_ln_elu<<<N, 256>>>(ln3_g, ln3_b, -1, BUF_X3, 256);

    // ---- pooling + classifier ----
    k_pool_init<<<(NGR * 256 + 255) / 256, 256>>>();
    k_pool_scatter<<<(N * 256 + 255) / 256, 256>>>(batch, N);
    k_classify<<<NGR, 128>>>(cls1_w, cls1_b, cls2_w, cls2_b, out);
}

// round 9
// speedup vs baseline: 1.9052x; 1.5091x over previous
#include <cuda_runtime.h>
#include <cuda_bf16.h>
#include <math.h>

// ---------------- problem constants ----------------
#define MAXN 20000
#define MAXE 320000
#define MAXET (MAXN + MAXE)
#define NGR 32

// ---------------- device scratch (no allocs allowed) ----------------
__device__ float g_h768[MAXN * 768];
__device__ float g_T[(size_t)MAXN * 1024];
__device__ float g_G[(size_t)MAXN * 1024];
__device__ float g_x1[(size_t)MAXN * 1024];
__device__ float g_x2[(size_t)MAXN * 1024];
__device__ float g_x3[MAXN * 256];
__device__ float g_es[MAXN * 4];
__device__ float g_ed[MAXN * 4];
__device__ int   g_deg[MAXN];
__device__ int   g_off[MAXN + 1];
__device__ int   g_cur[MAXN];
__device__ int   g_csr[MAXET];
__device__ float g_psum[NGR * 256];
__device__ float g_pmax[NGR * 256];
__device__ int   g_pcnt[NGR];

// packed bf16x2 hi/lo buffers (pre-split once per layer)
__device__ unsigned g_pa_h[(size_t)MAXN * 512];   // A packed: [m][kpair], KP<=512
__device__ unsigned g_pa_l[(size_t)MAXN * 512];
__device__ unsigned g_pw_h[1024 * 512];           // W packed: [n][kpair], N<=1024
__device__ unsigned g_pw_l[1024 * 512];

// Device-side buffer table: kernel_launch stays pure kernel launches.
#define BUF_H768 0
#define BUF_T    1
#define BUF_G    2
#define BUF_X1   3
#define BUF_X2   4
#define BUF_X3   5
__device__ float* const g_fptr[6] = { g_h768, g_T, g_G, g_x1, g_x2, g_x3 };

// ---------------- helpers ----------------
__device__ __forceinline__ float atomicMaxF(float* addr, float value) {
    if (value >= 0.f)
        return __int_as_float(atomicMax((int*)addr, __float_as_int(value)));
    else
        return __uint_as_float(atomicMin((unsigned int*)addr, __float_as_uint(value)));
}

__device__ __forceinline__ void bf_split(float x, unsigned short& hi, unsigned short& lo) {
    __nv_bfloat16 h = __float2bfloat16_rn(x);
    float hf = __bfloat162float(h);
    __nv_bfloat16 l = __float2bfloat16_rn(x - hf);
    hi = __bfloat16_as_ushort(h);
    lo = __bfloat16_as_ushort(l);
}

__device__ __forceinline__ void mma_bf16(float c[4], unsigned a0, unsigned a1, unsigned a2, unsigned a3,
                                         unsigned b0, unsigned b1) {
    asm volatile(
        "mma.sync.aligned.m16n8k16.row.col.f32.bf16.bf16.f32 "
        "{%0,%1,%2,%3}, {%4,%5,%6,%7}, {%8,%9}, {%0,%1,%2,%3};"
        : "+f"(c[0]), "+f"(c[1]), "+f"(c[2]), "+f"(c[3])
        : "r"(a0), "r"(a1), "r"(a2), "r"(a3), "r"(b0), "r"(b1));
}

// ---------------- CSR build ----------------
__global__ void k_zero_deg(int n) {
    int i = blockIdx.x * 256 + threadIdx.x;
    if (i < n) g_deg[i] = 0;
}

__global__ void k_count_deg(const int* __restrict__ ei, int E, int N) {
    int i = blockIdx.x * 256 + threadIdx.x;
    if (i >= E + N) return;
    int dst = (i < E) ? ei[E + i] : (i - E);
    atomicAdd(&g_deg[dst], 1);
}

__global__ void __launch_bounds__(1024) k_scan_deg(int n) {
    const int NT = 1024;
    int tid = threadIdx.x;
    int chunk = (n + NT - 1) / NT;
    int b0 = tid * chunk;
    int lsum = 0;
    for (int i = 0; i < chunk; i++) {
        int j = b0 + i;
        if (j < n) lsum += g_deg[j];
    }
    __shared__ int s[NT];
    s[tid] = lsum;
    __syncthreads();
    for (int o = 1; o < NT; o <<= 1) {
        int t = (tid >= o) ? s[tid - o] : 0;
        __syncthreads();
        s[tid] += t;
        __syncthreads();
    }
    int run = s[tid] - lsum;  // exclusive prefix
    for (int i = 0; i < chunk; i++) {
        int j = b0 + i;
        if (j < n) { g_off[j] = run; g_cur[j] = run; run += g_deg[j]; }
    }
    if (tid == NT - 1) g_off[n] = s[NT - 1];
}

__global__ void k_scatter_edges(const int* __restrict__ ei, int E, int N) {
    int i = blockIdx.x * 256 + threadIdx.x;
    if (i >= E + N) return;
    int src, dst;
    if (i < E) { src = ei[i]; dst = ei[E + i]; }
    else       { src = i - E; dst = i - E; }
    int pos = atomicAdd(&g_cur[dst], 1);
    g_csr[pos] = src;
}

// ---------------- pack kernels: fp32 -> bf16 hi/lo packed pairs ----------------
// A: [M,K] row-major -> g_pa_{h,l}[m][kp], kp = k/2 (k even in low half)
__global__ void k_packA(const float* __restrict__ Aext, int a_id, int MKP) {
    const float* __restrict__ A = Aext ? Aext : g_fptr[a_id];
    int i = blockIdx.x * 256 + threadIdx.x;
    if (i >= MKP) return;
    float2 v = *(const float2*)(A + (size_t)i * 2);
    unsigned short h0, l0, h1, l1;
    bf_split(v.x, h0, l0);
    bf_split(v.y, h1, l1);
    g_pa_h[i] = (unsigned)h0 | ((unsigned)h1 << 16);
    g_pa_l[i] = (unsigned)l0 | ((unsigned)l1 << 16);
}

// W: [K,N] row-major -> g_pw_{h,l}[n][kp]
__global__ void k_packW(const float* __restrict__ W, int N, int KP) {
    int u = blockIdx.x * 256 + threadIdx.x;  // u = kp*N + n (reads coalesced)
    if (u >= N * KP) return;
    int kp = u / N, n = u - kp * N;
    float a = W[(size_t)(2 * kp) * N + n];
    float b = W[(size_t)(2 * kp + 1) * N + n];
    unsigned short ha, la, hb, lb;
    bf_split(a, ha, la);
    bf_split(b, hb, lb);
    g_pw_h[(size_t)n * KP + kp] = (unsigned)ha | ((unsigned)hb << 16);
    g_pw_l[(size_t)n * KP + kp] = (unsigned)la | ((unsigned)lb << 16);
}

// ---------------- Tensor-core GEMM (pre-packed bf16 hi/lo, 3 terms) ----------------
// Block tile 128x128x32, 8 warps (2x4), warp tile 64x32 via m16n8k16.bf16.
// Reads g_pa_* and g_pw_* packed buffers. K % 32 == 0, N % 128 == 0.
#define GM 128
#define GN 128
#define SLD 20   // smem row stride (uint32): conflict-free fragment reads
template <int ACT>
__global__ void __launch_bounds__(256) k_tgemm(const float* __restrict__ bias, int c_id,
                                               int M, int N, int K) {
    float* __restrict__ C = g_fptr[c_id];
    const int KP = K >> 1;

    __shared__ unsigned Ah[GM][SLD];
    __shared__ unsigned Al[GM][SLD];
    __shared__ unsigned Wh[GN][SLD];
    __shared__ unsigned Wl[GN][SLD];

    int tid = threadIdx.x, wid = tid >> 5, lane = tid & 31;
    int warp_m = wid & 1, warp_n = wid >> 1;   // 2 x 4 warps
    int row0 = blockIdx.y * GM, col0 = blockIdx.x * GN;
    int qr = lane >> 2, qc = lane & 3;         // quad row / col

    float acc[4][4][4] = {};

    const int r_ld = tid >> 1;                 // 0..127 (row handled by this thread)
    const int c4_ld = (tid & 1) * 8;           // kpair offset 0 or 8

    for (int kp0 = 0; kp0 < KP; kp0 += 16) {
        // ---- load packed tiles: per thread one row-half (8 kpairs = 2 uint4) each ----
        {
            int gr = row0 + r_ld;
            if (gr < M) {
                const unsigned* pah = &g_pa_h[(size_t)gr * KP + kp0 + c4_ld];
                const unsigned* pal = &g_pa_l[(size_t)gr * KP + kp0 + c4_ld];
                *(uint4*)&Ah[r_ld][c4_ld] = *(const uint4*)pah;
                *(uint4*)&Ah[r_ld][c4_ld + 4] = *(const uint4*)(pah + 4);
                *(uint4*)&Al[r_ld][c4_ld] = *(const uint4*)pal;
                *(uint4*)&Al[r_ld][c4_ld + 4] = *(const uint4*)(pal + 4);
            } else {
                uint4 z = make_uint4(0, 0, 0, 0);
                *(uint4*)&Ah[r_ld][c4_ld] = z;
                *(uint4*)&Ah[r_ld][c4_ld + 4] = z;
                *(uint4*)&Al[r_ld][c4_ld] = z;
                *(uint4*)&Al[r_ld][c4_ld + 4] = z;
            }
            const unsigned* pwh = &g_pw_h[(size_t)(col0 + r_ld) * KP + kp0 + c4_ld];
            const unsigned* pwl = &g_pw_l[(size_t)(col0 + r_ld) * KP + kp0 + c4_ld];
            *(uint4*)&Wh[r_ld][c4_ld] = *(const uint4*)pwh;
            *(uint4*)&Wh[r_ld][c4_ld + 4] = *(const uint4*)(pwh + 4);
            *(uint4*)&Wl[r_ld][c4_ld] = *(const uint4*)pwl;
            *(uint4*)&Wl[r_ld][c4_ld + 4] = *(const uint4*)(pwl + 4);
        }
        __syncthreads();

        // ---- 2 x k16 steps ----
#pragma unroll
        for (int kk = 0; kk < 2; kk++) {
            int kb = kk * 8;  // kpair offset
            unsigned ah[4][4], al[4][4];
#pragma unroll
            for (int i = 0; i < 4; i++) {
                int r = warp_m * 64 + i * 16;
                ah[i][0] = Ah[r + qr][kb + qc];
                ah[i][1] = Ah[r + qr + 8][kb + qc];
                ah[i][2] = Ah[r + qr][kb + qc + 4];
                ah[i][3] = Ah[r + qr + 8][kb + qc + 4];
                al[i][0] = Al[r + qr][kb + qc];
                al[i][1] = Al[r + qr + 8][kb + qc];
                al[i][2] = Al[r + qr][kb + qc + 4];
                al[i][3] = Al[r + qr + 8][kb + qc + 4];
            }
            unsigned bh[4][2], bl[4][2];
#pragma unroll
            for (int j = 0; j < 4; j++) {
                int c = warp_n * 32 + j * 8 + qr;
                bh[j][0] = Wh[c][kb + qc];
                bh[j][1] = Wh[c][kb + qc + 4];
                bl[j][0] = Wl[c][kb + qc];
                bl[j][1] = Wl[c][kb + qc + 4];
            }
#pragma unroll
            for (int i = 0; i < 4; i++)
#pragma unroll
                for (int j = 0; j < 4; j++) {
                    mma_bf16(acc[i][j], ah[i][0], ah[i][1], ah[i][2], ah[i][3], bh[j][0], bh[j][1]);
                    mma_bf16(acc[i][j], al[i][0], al[i][1], al[i][2], al[i][3], bh[j][0], bh[j][1]);
                    mma_bf16(acc[i][j], ah[i][0], ah[i][1], ah[i][2], ah[i][3], bl[j][0], bl[j][1]);
                }
        }
        __syncthreads();
    }

    // Epilogue
#pragma unroll
    for (int i = 0; i < 4; i++) {
#pragma unroll
        for (int j = 0; j < 4; j++) {
            int rg = row0 + warp_m * 64 + i * 16 + qr;
            int cg = col0 + warp_n * 32 + j * 8 + qc * 2;
            float b0v = 0.f, b1v = 0.f;
            if (bias) { b0v = bias[cg]; b1v = bias[cg + 1]; }
#pragma unroll
            for (int half = 0; half < 2; half++) {
                int r = rg + half * 8;
                if (r >= M) continue;
                float vx = acc[i][j][half * 2 + 0] + b0v;
                float vy = acc[i][j][half * 2 + 1] + b1v;
                if (ACT == 1) {
                    vx = vx > 0.f ? vx : (expf(vx) - 1.0f);
                    vy = vy > 0.f ? vy : (expf(vy) - 1.0f);
                }
                float2 v2 = make_float2(vx, vy);
                *(float2*)(C + (size_t)r * N + cg) = v2;
            }
        }
    }
}

// ---------------- attention dot products ----------------
__global__ void k_att_dots(const float* __restrict__ as_, const float* __restrict__ ad_,
                           int NH, int H, int C) {
    const float* __restrict__ T = g_T;
    int gw = (blockIdx.x * blockDim.x + threadIdx.x) >> 5;
    int lane = threadIdx.x & 31;
    if (gw >= NH) return;
    int n = gw / H, h = gw - n * H;
    const float* row = T + (size_t)n * H * C + (size_t)h * C;
    float a = 0.f, d = 0.f;
    for (int c = lane; c < C; c += 32) {
        float v = row[c];
        a += v * as_[h * C + c];
        d += v * ad_[h * C + c];
    }
    for (int o = 16; o; o >>= 1) {
        a += __shfl_xor_sync(0xffffffffu, a, o);
        d += __shfl_xor_sync(0xffffffffu, d, o);
    }
    if (lane == 0) { g_es[gw] = a; g_ed[gw] = d; }
}

// ---------------- GAT aggregation (per-dst-node softmax + weighted gather) ----------------
template <int H, int CPT>
__global__ void __launch_bounds__(256) k_gat_agg(const float* __restrict__ bias) {
    const int F = 256 * CPT;  // = H*256
    const float* __restrict__ T = g_T;
    const float* __restrict__ es = g_es;
    float* __restrict__ out = g_G;
    int node = blockIdx.x;
    int tid = threadIdx.x;
    int lane = tid & 31, wid = tid >> 5;
    int beg = g_off[node], end = g_off[node + 1];

    float edv[H];
#pragma unroll
    for (int h = 0; h < H; h++) edv[h] = g_ed[node * H + h];

    __shared__ float s_red[8][H];
    __shared__ float s_hmax[H];
    __shared__ float s_hden[H];

    // pass 1: per-head max logit
    float lmax[H];
#pragma unroll
    for (int h = 0; h < H; h++) lmax[h] = -INFINITY;
    for (int e = beg + tid; e < end; e += 256) {
        int s = g_csr[e];
        if (H == 4) {
            float4 e4 = *(const float4*)(es + s * 4);
            float l0 = e4.x + edv[0]; l0 = l0 > 0.f ? l0 : 0.2f * l0; lmax[0] = fmaxf(lmax[0], l0);
            float l1 = e4.y + edv[1]; l1 = l1 > 0.f ? l1 : 0.2f * l1; lmax[1] = fmaxf(lmax[1], l1);
            float l2 = e4.z + edv[2]; l2 = l2 > 0.f ? l2 : 0.2f * l2; lmax[2] = fmaxf(lmax[2], l2);
            float l3 = e4.w + edv[3]; l3 = l3 > 0.f ? l3 : 0.2f * l3; lmax[3] = fmaxf(lmax[3], l3);
        } else {
            float l = es[s * H] + edv[0];
            l = l > 0.f ? l : 0.2f * l;
            lmax[0] = fmaxf(lmax[0], l);
        }
    }
#pragma unroll
    for (int h = 0; h < H; h++)
        for (int o = 16; o; o >>= 1) lmax[h] = fmaxf(lmax[h], __shfl_xor_sync(0xffffffffu, lmax[h], o));
    if (lane == 0) {
#pragma unroll
        for (int h = 0; h < H; h++) s_red[wid][h] = lmax[h];
    }
    __syncthreads();
    if (tid == 0) {
#pragma unroll
        for (int h = 0; h < H; h++) {
            float m = s_red[0][h];
            for (int w = 1; w < 8; w++) m = fmaxf(m, s_red[w][h]);
            s_hmax[h] = m;
        }
    }
    __syncthreads();

    // pass 2: denominator
    float lden[H] = {};
    for (int e = beg + tid; e < end; e += 256) {
        int s = g_csr[e];
        if (H == 4) {
            float4 e4 = *(const float4*)(es + s * 4);
            float l0 = e4.x + edv[0]; l0 = l0 > 0.f ? l0 : 0.2f * l0; lden[0] += expf(l0 - s_hmax[0]);
            float l1 = e4.y + edv[1]; l1 = l1 > 0.f ? l1 : 0.2f * l1; lden[1] += expf(l1 - s_hmax[1]);
            float l2 = e4.z + edv[2]; l2 = l2 > 0.f ? l2 : 0.2f * l2; lden[2] += expf(l2 - s_hmax[2]);
            float l3 = e4.w + edv[3]; l3 = l3 > 0.f ? l3 : 0.2f * l3; lden[3] += expf(l3 - s_hmax[3]);
        } else {
            float l = es[s * H] + edv[0];
            l = l > 0.f ? l : 0.2f * l;
            lden[0] += expf(l - s_hmax[0]);
        }
    }
#pragma unroll
    for (int h = 0; h < H; h++)
        for (int o = 16; o; o >>= 1) lden[h] += __shfl_xor_sync(0xffffffffu, lden[h], o);
    if (lane == 0) {
#pragma unroll
        for (int h = 0; h < H; h++) s_red[wid][h] = lden[h];
    }
    __syncthreads();
    if (tid == 0) {
#pragma unroll
        for (int h = 0; h < H; h++) {
            float m = 0.f;
            for (int w = 0; w < 8; w++) m += s_red[w][h];
            s_hden[h] = m;
        }
    }
    __syncthreads();

    // pass 3: weighted gather
    float acc[CPT] = {};
    __shared__ int s_src[256];
    __shared__ float s_alpha[256 * H];
    for (int cb = beg; cb < end; cb += 256) {
        int cn = min(256, end - cb);
        if (tid < cn) {
            int s = g_csr[cb + tid];
            s_src[tid] = s;
#pragma unroll
            for (int h = 0; h < H; h++) {
                float l = es[s * H + h] + edv[h];
                l = l > 0.f ? l : 0.2f * l;
                s_alpha[tid * H + h] = expf(l - s_hmax[h]) / (s_hden[h] + 1e-16f);
            }
        }
        __syncthreads();
        if (CPT == 4) {
            const int head = tid >> 6;
            for (int j = 0; j < cn; j++) {
                int s = s_src[j];
                float alpha = s_alpha[j * H + head];
                float4 v = *(const float4*)(T + (size_t)s * F + tid * 4);
                acc[0] += alpha * v.x;
                acc[1] += alpha * v.y;
                acc[2] += alpha * v.z;
                acc[3] += alpha * v.w;
            }
        } else {
            for (int j = 0; j < cn; j++) {
                int s = s_src[j];
                float alpha = s_alpha[j * H];
                acc[0] += alpha * T[(size_t)s * F + tid];
            }
        }
        __syncthreads();
    }
#pragma unroll
    for (int q = 0; q < CPT; q++) {
        int c = tid * CPT + q;
        out[(size_t)node * F + c] = acc[q] + bias[c];
    }
}

// ---------------- LayerNorm + ELU (+ optional residual added AFTER elu) ----------------
__global__ void __launch_bounds__(256) k_ln_elu(const float* __restrict__ g,
                                                const float* __restrict__ b,
                                                int res_id, int out_id, int F) {
    const float* __restrict__ in = g_G;
    const float* __restrict__ res = (res_id >= 0) ? g_fptr[res_id] : nullptr;
    float* __restrict__ out = g_fptr[out_id];
    int node = blockIdx.x, tid = threadIdx.x;
    const float* row = in + (size_t)node * F;
    int nv = F >> 2;
    float s = 0.f, s2 = 0.f;
    for (int q = tid; q < nv; q += 256) {
        float4 v = *(const float4*)(row + q * 4);
        s += v.x + v.y + v.z + v.w;
        s2 += v.x * v.x + v.y * v.y + v.z * v.z + v.w * v.w;
    }
    __shared__ float sh[8], sh2[8];
    for (int o = 16; o; o >>= 1) {
        s += __shfl_xor_sync(0xffffffffu, s, o);
        s2 += __shfl_xor_sync(0xffffffffu, s2, o);
    }
    if ((tid & 31) == 0) { sh[tid >> 5] = s; sh2[tid >> 5] = s2; }
    __syncthreads();
    __shared__ float smean, sinv;
    if (tid == 0) {
        float ts = 0.f, t2 = 0.f;
        for (int w = 0; w < 8; w++) { ts += sh[w]; t2 += sh2[w]; }
        float mean = ts / F;
        float var = t2 / F - mean * mean;
        if (var < 0.f) var = 0.f;
        smean = mean;
        sinv = rsqrtf(var + 1e-5f);
    }
    __syncthreads();
    float mean = smean, inv = sinv;
    for (int q = tid; q < nv; q += 256) {
        int c = q * 4;
        float4 v = *(const float4*)(row + c);
        float4 gg = *(const float4*)(g + c);
        float4 bb = *(const float4*)(b + c);
        v.x = (v.x - mean) * inv * gg.x + bb.x;
        v.y = (v.y - mean) * inv * gg.y + bb.y;
        v.z = (v.z - mean) * inv * gg.z + bb.z;
        v.w = (v.w - mean) * inv * gg.w + bb.w;
        v.x = v.x > 0.f ? v.x : (expf(v.x) - 1.0f);
        v.y = v.y > 0.f ? v.y : (expf(v.y) - 1.0f);
        v.z = v.z > 0.f ? v.z : (expf(v.z) - 1.0f);
        v.w = v.w > 0.f ? v.w : (expf(v.w) - 1.0f);
        if (res) {
            float4 rr = *(const float4*)(res + (size_t)node * F + c);
            v.x += rr.x; v.y += rr.y; v.z += rr.z; v.w += rr.w;
        }
        *(float4*)(out + (size_t)node * F + c) = v;
    }
}

// ---------------- pooling ----------------
__global__ void k_pool_init() {
    int i = blockIdx.x * 256 + threadIdx.x;
    if (i < NGR * 256) { g_psum[i] = 0.f; g_pmax[i] = -INFINITY; }
    if (i < NGR) g_pcnt[i] = 0;
}

__global__ void k_pool_scatter(const int* __restrict__ batch, int N) {
    int i = blockIdx.x * 256 + threadIdx.x;
    if (i >= N * 256) return;
    int n = i >> 8, c = i & 255;
    int gph = batch[n];
    float v = g_x3[(size_t)n * 256 + c];
    atomicAdd(&g_psum[gph * 256 + c], v);
    atomicMaxF(&g_pmax[gph * 256 + c], v);
    if (c == 0) atomicAdd(&g_pcnt[gph], 1);
}

// ---------------- classifier head ----------------
__global__ void __launch_bounds__(128) k_classify(const float* __restrict__ w1, const float* __restrict__ b1,
                                                  const float* __restrict__ w2, const float* __restrict__ b2,
                                                  float* __restrict__ out) {
    int gph = blockIdx.x, tid = threadIdx.x;
    __shared__ float p[768];
    float cnt = (float)max(g_pcnt[gph], 1);
    for (int j = tid; j < 256; j += 128) {
        float sm = g_psum[gph * 256 + j];
        p[j] = sm / cnt;
        p[256 + j] = g_pmax[gph * 256 + j];
        p[512 + j] = sm;
    }
    __syncthreads();
    float h = b1[tid];
    for (int j = 0; j < 768; j++) h += p[j] * w1[j * 128 + tid];
    h = h > 0.f ? h : 0.f;
    float part = h * w2[tid];
    for (int o = 16; o; o >>= 1) part += __shfl_xor_sync(0xffffffffu, part, o);
    __shared__ float sr[4];
    if ((tid & 31) == 0) sr[tid >> 5] = part;
    __syncthreads();
    if (tid == 0) out[gph] = sr[0] + sr[1] + sr[2] + sr[3] + b2[0];
}

// ---------------- launch (pure kernel launches; graph-capture safe) ----------------
extern "C" void kernel_launch(void* const* d_in, const int* in_sizes, int n_in,
                              void* d_out, int out_size) {
    const float* x = (const float*)d_in[0];
    const int* ei = (const int*)d_in[1];
    const int* batch = (const int*)d_in[2];
    const float* proj_w = (const float*)d_in[3];
    const float* proj_b = (const float*)d_in[4];
    const float* gat1_w = (const float*)d_in[5];
    const float* att1_src = (const float*)d_in[6];
    const float* att1_dst = (const float*)d_in[7];
    const float* gat1_b = (const float*)d_in[8];
    const float* ln1_g = (const float*)d_in[9];
    const float* ln1_b = (const float*)d_in[10];
    const float* gat2_w = (const float*)d_in[11];
    const float* att2_src = (const float*)d_in[12];
    const float* att2_dst = (const float*)d_in[13];
    const float* gat2_b = (const float*)d_in[14];
    const float* ln2_g = (const float*)d_in[15];
    const float* ln2_b = (const float*)d_in[16];
    const float* gat3_w = (const float*)d_in[17];
    const float* att3_src = (const float*)d_in[18];
    const float* att3_dst = (const float*)d_in[19];
    const float* gat3_b = (const float*)d_in[20];
    const float* ln3_g = (const float*)d_in[21];
    const float* ln3_b = (const float*)d_in[22];
    const float* cls1_w = (const float*)d_in[23];
    const float* cls1_b = (const float*)d_in[24];
    const float* cls2_w = (const float*)d_in[25];
    const float* cls2_b = (const float*)d_in[26];
    float* out = (float*)d_out;

    int N = in_sizes[0] / 768;
    int E = in_sizes[1] / 2;
    int ET = E + N;

    // ---- CSR build (dst-grouped incoming edges incl. self-loops) ----
    k_zero_deg<<<(N + 255) / 256, 256>>>(N);
    k_count_deg<<<(ET + 255) / 256, 256>>>(ei, E, N);
    k_scan_deg<<<1, 1024>>>(N);
    k_scatter_edges<<<(ET + 255) / 256, 256>>>(ei, E, N);

    dim3 thr(256);
    int mgrid = (N + GM - 1) / GM;
    int mkp384 = N * 384, mkp512 = N * 512;

    // ---- h = elu(x @ proj_w + proj_b) ----
    k_packW<<<(768 * 384 + 255) / 256, thr>>>(proj_w, 768, 384);
    k_packA<<<(mkp384 + 255) / 256, thr>>>(x, 0, mkp384);
    k_tgemm<1><<<dim3(768 / GN, mgrid), thr>>>(proj_b, BUF_H768, N, 768, 768);

    // ---- GAT layer 1: 768 -> 4x256 concat ----
    k_packW<<<(1024 * 384 + 255) / 256, thr>>>(gat1_w, 1024, 384);
    k_packA<<<(mkp384 + 255) / 256, thr>>>(nullptr, BUF_H768, mkp384);
    k_tgemm<0><<<dim3(1024 / GN, mgrid), thr>>>(nullptr, BUF_T, N, 1024, 768);
    k_att_dots<<<(N * 4 * 32 + 255) / 256, 256>>>(att1_src, att1_dst, N * 4, 4, 256);
    k_gat_agg<4, 4><<<N, 256>>>(gat1_b);
    k_ln_elu<<<N, 256>>>(ln1_g, ln1_b, -1, BUF_X1, 1024);

    // ---- GAT layer 2: 1024 -> 4x256 concat, residual ----
    k_packW<<<(1024 * 512 + 255) / 256, thr>>>(gat2_w, 1024, 512);
    k_packA<<<(mkp512 + 255) / 256, thr>>>(nullptr, BUF_X1, mkp512);
    k_tgemm<0><<<dim3(1024 / GN, mgrid), thr>>>(nullptr, BUF_T, N, 1024, 1024);
    k_att_dots<<<(N * 4 * 32 + 255) / 256, 256>>>(att2_src, att2_dst, N * 4, 4, 256);
    k_gat_agg<4, 4><<<N, 256>>>(gat2_b);
    k_ln_elu<<<N, 256>>>(ln2_g, ln2_b, BUF_X1, BUF_X2, 1024);

    // ---- GAT layer 3: 1024 -> 1x256 ----
    k_packW<<<(256 * 512 + 255) / 256, thr>>>(gat3_w, 256, 512);
    k_packA<<<(mkp512 + 255) / 256, thr>>>(nullptr, BUF_X2, mkp512);
    k_tgemm<0><<<dim3(256 / GN, mgrid), thr>>>(nullptr, BUF_T, N, 256, 1024);
    k_att_dots<<<(N * 1 * 32 + 255) / 256, 256>>>(att3_src, att3_dst, N * 1, 1, 256);
    k_gat_agg<1, 1><<<N, 256>>>(gat3_b);
    k_ln_elu<<<N, 256>>>(ln3_g, ln3_b, -1, BUF_X3, 256);

    // ---- pooling + classifier ----
    k_pool_init<<<(NGR * 256 + 255) / 256, 256>>>();
    k_pool_scatter<<<(N * 256 + 255) / 256, 256>>>(batch, N);
    k_classify<<<NGR, 128>>>(cls1_w, cls1_b, cls2_w, cls2_b, out);
}

// round 10
// speedup vs baseline: 2.0775x; 1.0904x over previous
#include <cuda_runtime.h>
#include <cuda_bf16.h>
#include <math.h>

// ---------------- problem constants ----------------
#define MAXN 20000
#define MAXE 320000
#define MAXET (MAXN + MAXE)
#define NGR 32

// ---------------- device scratch (no allocs allowed) ----------------
__device__ float g_h768[MAXN * 768];
__device__ float g_T[(size_t)MAXN * 1024];
__device__ float g_G[(size_t)MAXN * 1024];
__device__ float g_x1[(size_t)MAXN * 1024];
__device__ float g_x2[(size_t)MAXN * 1024];
__device__ float g_x3[MAXN * 256];
__device__ float g_es[MAXN * 4];
__device__ float g_ed[MAXN * 4];
__device__ int   g_deg[MAXN];
__device__ int   g_off[MAXN + 1];
__device__ int   g_cur[MAXN];
__device__ int   g_csr[MAXET];
__device__ float g_psum[NGR * 256];
__device__ float g_pmax[NGR * 256];
__device__ int   g_pcnt[NGR];

// packed bf16x2 hi/lo buffers (pre-split once per layer)
__device__ unsigned g_pa_h[(size_t)MAXN * 512];   // A packed: [m][kpair], KP<=512
__device__ unsigned g_pa_l[(size_t)MAXN * 512];
__device__ unsigned g_pw_h[1024 * 512];           // W packed: [n][kpair], N<=1024
__device__ unsigned g_pw_l[1024 * 512];

// Device-side buffer table: kernel_launch stays pure kernel launches.
#define BUF_H768 0
#define BUF_T    1
#define BUF_G    2
#define BUF_X1   3
#define BUF_X2   4
#define BUF_X3   5
__device__ float* const g_fptr[6] = { g_h768, g_T, g_G, g_x1, g_x2, g_x3 };

// ---------------- helpers ----------------
__device__ __forceinline__ float atomicMaxF(float* addr, float value) {
    if (value >= 0.f)
        return __int_as_float(atomicMax((int*)addr, __float_as_int(value)));
    else
        return __uint_as_float(atomicMin((unsigned int*)addr, __float_as_uint(value)));
}

__device__ __forceinline__ void bf_split(float x, unsigned short& hi, unsigned short& lo) {
    __nv_bfloat16 h = __float2bfloat16_rn(x);
    float hf = __bfloat162float(h);
    __nv_bfloat16 l = __float2bfloat16_rn(x - hf);
    hi = __bfloat16_as_ushort(h);
    lo = __bfloat16_as_ushort(l);
}

__device__ __forceinline__ void mma_bf16(float c[4], unsigned a0, unsigned a1, unsigned a2, unsigned a3,
                                         unsigned b0, unsigned b1) {
    asm volatile(
        "mma.sync.aligned.m16n8k16.row.col.f32.bf16.bf16.f32 "
        "{%0,%1,%2,%3}, {%4,%5,%6,%7}, {%8,%9}, {%0,%1,%2,%3};"
        : "+f"(c[0]), "+f"(c[1]), "+f"(c[2]), "+f"(c[3])
        : "r"(a0), "r"(a1), "r"(a2), "r"(a3), "r"(b0), "r"(b1));
}

__device__ __forceinline__ void cp16(unsigned dst_smem, const void* src, int src_size) {
    asm volatile("cp.async.cg.shared.global [%0], [%1], 16, %2;"
                 :: "r"(dst_smem), "l"(src), "r"(src_size));
}

// ---------------- CSR build ----------------
__global__ void k_zero_deg(int n) {
    int i = blockIdx.x * 256 + threadIdx.x;
    if (i < n) g_deg[i] = 0;
}

__global__ void k_count_deg(const int* __restrict__ ei, int E, int N) {
    int i = blockIdx.x * 256 + threadIdx.x;
    if (i >= E + N) return;
    int dst = (i < E) ? ei[E + i] : (i - E);
    atomicAdd(&g_deg[dst], 1);
}

__global__ void __launch_bounds__(1024) k_scan_deg(int n) {
    const int NT = 1024;
    int tid = threadIdx.x;
    int chunk = (n + NT - 1) / NT;
    int b0 = tid * chunk;
    int lsum = 0;
    for (int i = 0; i < chunk; i++) {
        int j = b0 + i;
        if (j < n) lsum += g_deg[j];
    }
    __shared__ int s[NT];
    s[tid] = lsum;
    __syncthreads();
    for (int o = 1; o < NT; o <<= 1) {
        int t = (tid >= o) ? s[tid - o] : 0;
        __syncthreads();
        s[tid] += t;
        __syncthreads();
    }
    int run = s[tid] - lsum;  // exclusive prefix
    for (int i = 0; i < chunk; i++) {
        int j = b0 + i;
        if (j < n) { g_off[j] = run; g_cur[j] = run; run += g_deg[j]; }
    }
    if (tid == NT - 1) g_off[n] = s[NT - 1];
}

__global__ void k_scatter_edges(const int* __restrict__ ei, int E, int N) {
    int i = blockIdx.x * 256 + threadIdx.x;
    if (i >= E + N) return;
    int src, dst;
    if (i < E) { src = ei[i]; dst = ei[E + i]; }
    else       { src = i - E; dst = i - E; }
    int pos = atomicAdd(&g_cur[dst], 1);
    g_csr[pos] = src;
}

// ---------------- pack kernels: fp32 -> bf16 hi/lo packed pairs ----------------
__global__ void k_packA(const float* __restrict__ Aext, int a_id, int MKP) {
    const float* __restrict__ A = Aext ? Aext : g_fptr[a_id];
    int i = blockIdx.x * 256 + threadIdx.x;
    if (i >= MKP) return;
    float2 v = *(const float2*)(A + (size_t)i * 2);
    unsigned short h0, l0, h1, l1;
    bf_split(v.x, h0, l0);
    bf_split(v.y, h1, l1);
    g_pa_h[i] = (unsigned)h0 | ((unsigned)h1 << 16);
    g_pa_l[i] = (unsigned)l0 | ((unsigned)l1 << 16);
}

__global__ void k_packW(const float* __restrict__ W, int N, int KP) {
    int u = blockIdx.x * 256 + threadIdx.x;  // u = kp*N + n (reads coalesced)
    if (u >= N * KP) return;
    int kp = u / N, n = u - kp * N;
    float a = W[(size_t)(2 * kp) * N + n];
    float b = W[(size_t)(2 * kp + 1) * N + n];
    unsigned short ha, la, hb, lb;
    bf_split(a, ha, la);
    bf_split(b, hb, lb);
    g_pw_h[(size_t)n * KP + kp] = (unsigned)ha | ((unsigned)hb << 16);
    g_pw_l[(size_t)n * KP + kp] = (unsigned)la | ((unsigned)lb << 16);
}

// ---------------- Tensor-core GEMM (pre-packed bf16 hi/lo, 3 terms, cp.async 2-stage) ----
// Block tile 128x128x32, 8 warps (2x4), warp tile 64x32 via m16n8k16.bf16.
#define GM 128
#define GN 128
#define SLD 20   // smem row stride (uint32): conflict-free fragment reads
template <int ACT>
__global__ void __launch_bounds__(256) k_tgemm(const float* __restrict__ bias, int c_id,
                                               int M, int N, int K) {
    float* __restrict__ C = g_fptr[c_id];
    const int KP = K >> 1;

    // [stage][Ah,Al,Wh,Wl][row][kpair]
    __shared__ __align__(16) unsigned SB[2][4][GM][SLD];

    int tid = threadIdx.x, wid = tid >> 5, lane = tid & 31;
    int warp_m = wid & 1, warp_n = wid >> 1;   // 2 x 4 warps
    int row0 = blockIdx.y * GM, col0 = blockIdx.x * GN;
    int qr = lane >> 2, qc = lane & 3;         // quad row / col

    float acc[4][4][4] = {};

    const int r_ld = tid >> 1;                 // 0..127
    const int c4_ld = (tid & 1) * 8;           // kpair offset 0 or 8
    const int gr = row0 + r_ld;
    const int asz = (gr < M) ? 16 : 0;
    const int gra = (gr < M) ? gr : (M - 1);   // clamped address (size 0 if OOB)
    const int wrow = col0 + r_ld;

    const int NTILES = KP >> 4;

    // issue loads for tile t into stage st
    auto load_tile = [&](int t, int st) {
        int kp0 = t << 4;
        const unsigned* pah = &g_pa_h[(size_t)gra * KP + kp0 + c4_ld];
        const unsigned* pal = &g_pa_l[(size_t)gra * KP + kp0 + c4_ld];
        cp16((unsigned)__cvta_generic_to_shared(&SB[st][0][r_ld][c4_ld]), pah, asz);
        cp16((unsigned)__cvta_generic_to_shared(&SB[st][0][r_ld][c4_ld + 4]), pah + 4, asz);
        cp16((unsigned)__cvta_generic_to_shared(&SB[st][1][r_ld][c4_ld]), pal, asz);
        cp16((unsigned)__cvta_generic_to_shared(&SB[st][1][r_ld][c4_ld + 4]), pal + 4, asz);
        const unsigned* pwh = &g_pw_h[(size_t)wrow * KP + kp0 + c4_ld];
        const unsigned* pwl = &g_pw_l[(size_t)wrow * KP + kp0 + c4_ld];
        cp16((unsigned)__cvta_generic_to_shared(&SB[st][2][r_ld][c4_ld]), pwh, 16);
        cp16((unsigned)__cvta_generic_to_shared(&SB[st][2][r_ld][c4_ld + 4]), pwh + 4, 16);
        cp16((unsigned)__cvta_generic_to_shared(&SB[st][3][r_ld][c4_ld]), pwl, 16);
        cp16((unsigned)__cvta_generic_to_shared(&SB[st][3][r_ld][c4_ld + 4]), pwl + 4, 16);
    };

    load_tile(0, 0);
    asm volatile("cp.async.commit_group;");

    for (int t = 0; t < NTILES; t++) {
        int p = t & 1;
        if (t + 1 < NTILES) load_tile(t + 1, p ^ 1);
        asm volatile("cp.async.commit_group;");
        asm volatile("cp.async.wait_group 1;");
        __syncthreads();

        unsigned (*Ah)[SLD] = SB[p][0];
        unsigned (*Al)[SLD] = SB[p][1];
        unsigned (*Wh)[SLD] = SB[p][2];
        unsigned (*Wl)[SLD] = SB[p][3];

#pragma unroll
        for (int kk = 0; kk < 2; kk++) {
            int kb = kk * 8;  // kpair offset
            unsigned ah[4][4], al[4][4];
#pragma unroll
            for (int i = 0; i < 4; i++) {
                int r = warp_m * 64 + i * 16;
                ah[i][0] = Ah[r + qr][kb + qc];
                ah[i][1] = Ah[r + qr + 8][kb + qc];
                ah[i][2] = Ah[r + qr][kb + qc + 4];
                ah[i][3] = Ah[r + qr + 8][kb + qc + 4];
                al[i][0] = Al[r + qr][kb + qc];
                al[i][1] = Al[r + qr + 8][kb + qc];
                al[i][2] = Al[r + qr][kb + qc + 4];
                al[i][3] = Al[r + qr + 8][kb + qc + 4];
            }
            unsigned bh[4][2], bl[4][2];
#pragma unroll
            for (int j = 0; j < 4; j++) {
                int c = warp_n * 32 + j * 8 + qr;
                bh[j][0] = Wh[c][kb + qc];
                bh[j][1] = Wh[c][kb + qc + 4];
                bl[j][0] = Wl[c][kb + qc];
                bl[j][1] = Wl[c][kb + qc + 4];
            }
#pragma unroll
            for (int i = 0; i < 4; i++)
#pragma unroll
                for (int j = 0; j < 4; j++) {
                    mma_bf16(acc[i][j], ah[i][0], ah[i][1], ah[i][2], ah[i][3], bh[j][0], bh[j][1]);
                    mma_bf16(acc[i][j], al[i][0], al[i][1], al[i][2], al[i][3], bh[j][0], bh[j][1]);
                    mma_bf16(acc[i][j], ah[i][0], ah[i][1], ah[i][2], ah[i][3], bl[j][0], bl[j][1]);
                }
        }
        __syncthreads();
    }

    // Epilogue
#pragma unroll
    for (int i = 0; i < 4; i++) {
#pragma unroll
        for (int j = 0; j < 4; j++) {
            int rg = row0 + warp_m * 64 + i * 16 + qr;
            int cg = col0 + warp_n * 32 + j * 8 + qc * 2;
            float b0v = 0.f, b1v = 0.f;
            if (bias) { b0v = bias[cg]; b1v = bias[cg + 1]; }
#pragma unroll
            for (int half = 0; half < 2; half++) {
                int r = rg + half * 8;
                if (r >= M) continue;
                float vx = acc[i][j][half * 2 + 0] + b0v;
                float vy = acc[i][j][half * 2 + 1] + b1v;
                if (ACT == 1) {
                    vx = vx > 0.f ? vx : (expf(vx) - 1.0f);
                    vy = vy > 0.f ? vy : (expf(vy) - 1.0f);
                }
                float2 v2 = make_float2(vx, vy);
                *(float2*)(C + (size_t)r * N + cg) = v2;
            }
        }
    }
}

// ---------------- attention dot products ----------------
__global__ void k_att_dots(const float* __restrict__ as_, const float* __restrict__ ad_,
                           int NH, int H, int C) {
    const float* __restrict__ T = g_T;
    int gw = (blockIdx.x * blockDim.x + threadIdx.x) >> 5;
    int lane = threadIdx.x & 31;
    if (gw >= NH) return;
    int n = gw / H, h = gw - n * H;
    const float* row = T + (size_t)n * H * C + (size_t)h * C;
    float a = 0.f, d = 0.f;
    for (int c = lane; c < C; c += 32) {
        float v = row[c];
        a += v * as_[h * C + c];
        d += v * ad_[h * C + c];
    }
    for (int o = 16; o; o >>= 1) {
        a += __shfl_xor_sync(0xffffffffu, a, o);
        d += __shfl_xor_sync(0xffffffffu, d, o);
    }
    if (lane == 0) { g_es[gw] = a; g_ed[gw] = d; }
}

// ---------------- GAT aggregation (per-dst-node softmax + weighted gather) ----------------
template <int H, int CPT>
__global__ void __launch_bounds__(256) k_gat_agg(const float* __restrict__ bias) {
    const int F = 256 * CPT;  // = H*256
    const float* __restrict__ T = g_T;
    const float* __restrict__ es = g_es;
    float* __restrict__ out = g_G;
    int node = blockIdx.x;
    int tid = threadIdx.x;
    int lane = tid & 31, wid = tid >> 5;
    int beg = g_off[node], end = g_off[node + 1];

    float edv[H];
#pragma unroll
    for (int h = 0; h < H; h++) edv[h] = g_ed[node * H + h];

    __shared__ float s_red[8][H];
    __shared__ float s_hmax[H];
    __shared__ float s_hden[H];

    // pass 1: per-head max logit
    float lmax[H];
#pragma unroll
    for (int h = 0; h < H; h++) lmax[h] = -INFINITY;
    for (int e = beg + tid; e < end; e += 256) {
        int s = g_csr[e];
        if (H == 4) {
            float4 e4 = *(const float4*)(es + s * 4);
            float l0 = e4.x + edv[0]; l0 = l0 > 0.f ? l0 : 0.2f * l0; lmax[0] = fmaxf(lmax[0], l0);
            float l1 = e4.y + edv[1]; l1 = l1 > 0.f ? l1 : 0.2f * l1; lmax[1] = fmaxf(lmax[1], l1);
            float l2 = e4.z + edv[2]; l2 = l2 > 0.f ? l2 : 0.2f * l2; lmax[2] = fmaxf(lmax[2], l2);
            float l3 = e4.w + edv[3]; l3 = l3 > 0.f ? l3 : 0.2f * l3; lmax[3] = fmaxf(lmax[3], l3);
        } else {
            float l = es[s * H] + edv[0];
            l = l > 0.f ? l : 0.2f * l;
            lmax[0] = fmaxf(lmax[0], l);
        }
    }
#pragma unroll
    for (int h = 0; h < H; h++)
        for (int o = 16; o; o >>= 1) lmax[h] = fmaxf(lmax[h], __shfl_xor_sync(0xffffffffu, lmax[h], o));
    if (lane == 0) {
#pragma unroll
        for (int h = 0; h < H; h++) s_red[wid][h] = lmax[h];
    }
    __syncthreads();
    if (tid == 0) {
#pragma unroll
        for (int h = 0; h < H; h++) {
            float m = s_red[0][h];
            for (int w = 1; w < 8; w++) m = fmaxf(m, s_red[w][h]);
            s_hmax[h] = m;
        }
    }
    __syncthreads();

    // pass 2: denominator
    float lden[H] = {};
    for (int e = beg + tid; e < end; e += 256) {
        int s = g_csr[e];
        if (H == 4) {
            float4 e4 = *(const float4*)(es + s * 4);
            float l0 = e4.x + edv[0]; l0 = l0 > 0.f ? l0 : 0.2f * l0; lden[0] += expf(l0 - s_hmax[0]);
            float l1 = e4.y + edv[1]; l1 = l1 > 0.f ? l1 : 0.2f * l1; lden[1] += expf(l1 - s_hmax[1]);
            float l2 = e4.z + edv[2]; l2 = l2 > 0.f ? l2 : 0.2f * l2; lden[2] += expf(l2 - s_hmax[2]);
            float l3 = e4.w + edv[3]; l3 = l3 > 0.f ? l3 : 0.2f * l3; lden[3] += expf(l3 - s_hmax[3]);
        } else {
            float l = es[s * H] + edv[0];
            l = l > 0.f ? l : 0.2f * l;
            lden[0] += expf(l - s_hmax[0]);
        }
    }
#pragma unroll
    for (int h = 0; h < H; h++)
        for (int o = 16; o; o >>= 1) lden[h] += __shfl_xor_sync(0xffffffffu, lden[h], o);
    if (lane == 0) {
#pragma unroll
        for (int h = 0; h < H; h++) s_red[wid][h] = lden[h];
    }
    __syncthreads();
    if (tid == 0) {
#pragma unroll
        for (int h = 0; h < H; h++) {
            float m = 0.f;
            for (int w = 0; w < 8; w++) m += s_red[w][h];
            s_hden[h] = m;
        }
    }
    __syncthreads();

    // pass 3: weighted gather (unrolled x4 for MLP)
    float acc[CPT] = {};
    __shared__ int s_src[256];
    __shared__ float s_alpha[256 * H];
    for (int cb = beg; cb < end; cb += 256) {
        int cn = min(256, end - cb);
        if (tid < cn) {
            int s = g_csr[cb + tid];
            s_src[tid] = s;
#pragma unroll
            for (int h = 0; h < H; h++) {
                float l = es[s * H + h] + edv[h];
                l = l > 0.f ? l : 0.2f * l;
                s_alpha[tid * H + h] = expf(l - s_hmax[h]) / (s_hden[h] + 1e-16f);
            }
        }
        __syncthreads();
        if (CPT == 4) {
            const int head = tid >> 6;
            int j = 0;
            for (; j + 4 <= cn; j += 4) {
                int s0 = s_src[j], s1 = s_src[j + 1], s2 = s_src[j + 2], s3 = s_src[j + 3];
                float a0 = s_alpha[(j + 0) * 4 + head];
                float a1 = s_alpha[(j + 1) * 4 + head];
                float a2 = s_alpha[(j + 2) * 4 + head];
                float a3 = s_alpha[(j + 3) * 4 + head];
                float4 v0 = *(const float4*)(T + (size_t)s0 * F + tid * 4);
                float4 v1 = *(const float4*)(T + (size_t)s1 * F + tid * 4);
                float4 v2 = *(const float4*)(T + (size_t)s2 * F + tid * 4);
                float4 v3 = *(const float4*)(T + (size_t)s3 * F + tid * 4);
                acc[0] += a0 * v0.x + a1 * v1.x + a2 * v2.x + a3 * v3.x;
                acc[1] += a0 * v0.y + a1 * v1.y + a2 * v2.y + a3 * v3.y;
                acc[2] += a0 * v0.z + a1 * v1.z + a2 * v2.z + a3 * v3.z;
                acc[3] += a0 * v0.w + a1 * v1.w + a2 * v2.w + a3 * v3.w;
            }
            for (; j < cn; j++) {
                int s = s_src[j];
                float alpha = s_alpha[j * 4 + head];
                float4 v = *(const float4*)(T + (size_t)s * F + tid * 4);
                acc[0] += alpha * v.x;
                acc[1] += alpha * v.y;
                acc[2] += alpha * v.z;
                acc[3] += alpha * v.w;
            }
        } else {
            int j = 0;
            for (; j + 4 <= cn; j += 4) {
                int s0 = s_src[j], s1 = s_src[j + 1], s2 = s_src[j + 2], s3 = s_src[j + 3];
                float a0 = s_alpha[j], a1 = s_alpha[j + 1], a2 = s_alpha[j + 2], a3 = s_alpha[j + 3];
                float v0 = T[(size_t)s0 * F + tid];
                float v1 = T[(size_t)s1 * F + tid];
                float v2 = T[(size_t)s2 * F + tid];
                float v3 = T[(size_t)s3 * F + tid];
                acc[0] += a0 * v0 + a1 * v1 + a2 * v2 + a3 * v3;
            }
            for (; j < cn; j++) {
                int s = s_src[j];
                acc[0] += s_alpha[j] * T[(size_t)s * F + tid];
            }
        }
        __syncthreads();
    }
#pragma unroll
    for (int q = 0; q < CPT; q++) {
        int c = tid * CPT + q;
        out[(size_t)node * F + c] = acc[q] + bias[c];
    }
}

// ---------------- LayerNorm + ELU (+ optional residual added AFTER elu) ----------------
__global__ void __launch_bounds__(256) k_ln_elu(const float* __restrict__ g,
                                                const float* __restrict__ b,
                                                int res_id, int out_id, int F) {
    const float* __restrict__ in = g_G;
    const float* __restrict__ res = (res_id >= 0) ? g_fptr[res_id] : nullptr;
    float* __restrict__ out = g_fptr[out_id];
    int node = blockIdx.x, tid = threadIdx.x;
    const float* row = in + (size_t)node * F;
    int nv = F >> 2;
    float s = 0.f, s2 = 0.f;
    for (int q = tid; q < nv; q += 256) {
        float4 v = *(const float4*)(row + q * 4);
        s += v.x + v.y + v.z + v.w;
        s2 += v.x * v.x + v.y * v.y + v.z * v.z + v.w * v.w;
    }
    __shared__ float sh[8], sh2[8];
    for (int o = 16; o; o >>= 1) {
        s += __shfl_xor_sync(0xffffffffu, s, o);
        s2 += __shfl_xor_sync(0xffffffffu, s2, o);
    }
    if ((tid & 31) == 0) { sh[tid >> 5] = s; sh2[tid >> 5] = s2; }
    __syncthreads();
    __shared__ float smean, sinv;
    if (tid == 0) {
        float ts = 0.f, t2 = 0.f;
        for (int w = 0; w < 8; w++) { ts += sh[w]; t2 += sh2[w]; }
        float mean = ts / F;
        float var = t2 / F - mean * mean;
        if (var < 0.f) var = 0.f;
        smean = mean;
        sinv = rsqrtf(var + 1e-5f);
    }
    __syncthreads();
    float mean = smean, inv = sinv;
    for (int q = tid; q < nv; q += 256) {
        int c = q * 4;
        float4 v = *(const float4*)(row + c);
        float4 gg = *(const float4*)(g + c);
        float4 bb = *(const float4*)(b + c);
        v.x = (v.x - mean) * inv * gg.x + bb.x;
        v.y = (v.y - mean) * inv * gg.y + bb.y;
        v.z = (v.z - mean) * inv * gg.z + bb.z;
        v.w = (v.w - mean) * inv * gg.w + bb.w;
        v.x = v.x > 0.f ? v.x : (expf(v.x) - 1.0f);
        v.y = v.y > 0.f ? v.y : (expf(v.y) - 1.0f);
        v.z = v.z > 0.f ? v.z : (expf(v.z) - 1.0f);
        v.w = v.w > 0.f ? v.w : (expf(v.w) - 1.0f);
        if (res) {
            float4 rr = *(const float4*)(res + (size_t)node * F + c);
            v.x += rr.x; v.y += rr.y; v.z += rr.z; v.w += rr.w;
        }
        *(float4*)(out + (size_t)node * F + c) = v;
    }
}

// ---------------- pooling ----------------
__global__ void k_pool_init() {
    int i = blockIdx.x * 256 + threadIdx.x;
    if (i < NGR * 256) { g_psum[i] = 0.f; g_pmax[i] = -INFINITY; }
    if (i < NGR) g_pcnt[i] = 0;
}

__global__ void k_pool_scatter(const int* __restrict__ batch, int N) {
    int i = blockIdx.x * 256 + threadIdx.x;
    if (i >= N * 256) return;
    int n = i >> 8, c = i & 255;
    int gph = batch[n];
    float v = g_x3[(size_t)n * 256 + c];
    atomicAdd(&g_psum[gph * 256 + c], v);
    atomicMaxF(&g_pmax[gph * 256 + c], v);
    if (c == 0) atomicAdd(&g_pcnt[gph], 1);
}

// ---------------- classifier head ----------------
__global__ void __launch_bounds__(128) k_classify(const float* __restrict__ w1, const float* __restrict__ b1,
                                                  const float* __restrict__ w2, const float* __restrict__ b2,
                                                  float* __restrict__ out) {
    int gph = blockIdx.x, tid = threadIdx.x;
    __shared__ float p[768];
    float cnt = (float)max(g_pcnt[gph], 1);
    for (int j = tid; j < 256; j += 128) {
        float sm = g_psum[gph * 256 + j];
        p[j] = sm / cnt;
        p[256 + j] = g_pmax[gph * 256 + j];
        p[512 + j] = sm;
    }
    __syncthreads();
    float h = b1[tid];
    for (int j = 0; j < 768; j++) h += p[j] * w1[j * 128 + tid];
    h = h > 0.f ? h : 0.f;
    float part = h * w2[tid];
    for (int o = 16; o; o >>= 1) part += __shfl_xor_sync(0xffffffffu, part, o);
    __shared__ float sr[4];
    if ((tid & 31) == 0) sr[tid >> 5] = part;
    __syncthreads();
    if (tid == 0) out[gph] = sr[0] + sr[1] + sr[2] + sr[3] + b2[0];
}

// ---------------- launch (pure kernel launches; graph-capture safe) ----------------
extern "C" void kernel_launch(void* const* d_in, const int* in_sizes, int n_in,
                              void* d_out, int out_size) {
    const float* x = (const float*)d_in[0];
    const int* ei = (const int*)d_in[1];
    const int* batch = (const int*)d_in[2];
    const float* proj_w = (const float*)d_in[3];
    const float* proj_b = (const float*)d_in[4];
    const float* gat1_w = (const float*)d_in[5];
    const float* att1_src = (const float*)d_in[6];
    const float* att1_dst = (const float*)d_in[7];
    const float* gat1_b = (const float*)d_in[8];
    const float* ln1_g = (const float*)d_in[9];
    const float* ln1_b = (const float*)d_in[10];
    const float* gat2_w = (const float*)d_in[11];
    const float* att2_src = (const float*)d_in[12];
    const float* att2_dst = (const float*)d_in[13];
    const float* gat2_b = (const float*)d_in[14];
    const float* ln2_g = (const float*)d_in[15];
    const float* ln2_b = (const float*)d_in[16];
    const float* gat3_w = (const float*)d_in[17];
    const float* att3_src = (const float*)d_in[18];
    const float* att3_dst = (const float*)d_in[19];
    const float* gat3_b = (const float*)d_in[20];
    const float* ln3_g = (const float*)d_in[21];
    const float* ln3_b = (const float*)d_in[22];
    const float* cls1_w = (const float*)d_in[23];
    const float* cls1_b = (const float*)d_in[24];
    const float* cls2_w = (const float*)d_in[25];
    const float* cls2_b = (const float*)d_in[26];
    float* out = (float*)d_out;

    int N = in_sizes[0] / 768;
    int E = in_sizes[1] / 2;
    int ET = E + N;

    dim3 thr(256);
    int mgrid = (N + GM - 1) / GM;
    int mkp384 = N * 384, mkp512 = N * 512;

    // ---- proj layer first; CSR build interleaved so launch #4 = k_tgemm (ncu) ----
    k_packW<<<(768 * 384 + 255) / 256, thr>>>(proj_w, 768, 384);
    k_packA<<<(mkp384 + 255) / 256, thr>>>(x, 0, mkp384);
    k_zero_deg<<<(N + 255) / 256, 256>>>(N);
    k_tgemm<1><<<dim3(768 / GN, mgrid), thr>>>(proj_b, BUF_H768, N, 768, 768);
    k_count_deg<<<(ET + 255) / 256, 256>>>(ei, E, N);
    k_scan_deg<<<1, 1024>>>(N);
    k_scatter_edges<<<(ET + 255) / 256, 256>>>(ei, E, N);

    // ---- GAT layer 1: 768 -> 4x256 concat ----
    k_packW<<<(1024 * 384 + 255) / 256, thr>>>(gat1_w, 1024, 384);
    k_packA<<<(mkp384 + 255) / 256, thr>>>(nullptr, BUF_H768, mkp384);
    k_tgemm<0><<<dim3(1024 / GN, mgrid), thr>>>(nullptr, BUF_T, N, 1024, 768);
    k_att_dots<<<(N * 4 * 32 + 255) / 256, 256>>>(att1_src, att1_dst, N * 4, 4, 256);
    k_gat_agg<4, 4><<<N, 256>>>(gat1_b);
    k_ln_elu<<<N, 256>>>(ln1_g, ln1_b, -1, BUF_X1, 1024);

    // ---- GAT layer 2: 1024 -> 4x256 concat, residual ----
    k_packW<<<(1024 * 512 + 255) / 256, thr>>>(gat2_w, 1024, 512);
    k_packA<<<(mkp512 + 255) / 256, thr>>>(nullptr, BUF_X1, mkp512);
    k_tgemm<0><<<dim3(1024 / GN, mgrid), thr>>>(nullptr, BUF_T, N, 1024, 1024);
    k_att_dots<<<(N * 4 * 32 + 255) / 256, 256>>>(att2_src, att2_dst, N * 4, 4, 256);
    k_gat_agg<4, 4><<<N, 256>>>(gat2_b);
    k_ln_elu<<<N, 256>>>(ln2_g, ln2_b, BUF_X1, BUF_X2, 1024);

    // ---- GAT layer 3: 1024 -> 1x256 ----
    k_packW<<<(256 * 512 + 255) / 256, thr>>>(gat3_w, 256, 512);
    k_packA<<<(mkp512 + 255) / 256, thr>>>(nullptr, BUF_X2, mkp512);
    k_tgemm<0><<<dim3(256 / GN, mgrid), thr>>>(nullptr, BUF_T, N, 256, 1024);
    k_att_dots<<<(N * 1 * 32 + 255) / 256, 256>>>(att3_src, att3_dst, N * 1, 1, 256);
    k_gat_agg<1, 1><<<N, 256>>>(gat3_b);
    k_ln_elu<<<N, 256>>>(ln3_g, ln3_b, -1, BUF_X3, 256);

    // ---- pooling + classifier ----
    k_pool_init<<<(NGR * 256 + 255) / 256, 256>>>();
    k_pool_scatter<<<(N * 256 + 255) / 256, 256>>>(batch, N);
    k_classify<<<NGR, 128>>>(cls1_w, cls1_b, cls2_w, cls2_b, out);
}

// round 16
// speedup vs baseline: 2.1511x; 1.0354x over previous
#include <cuda_runtime.h>
#include <cuda_bf16.h>
#include <stdint.h>
#include <math.h>

// ---------------- problem constants ----------------
#define MAXN 20000
#define MAXE 320000
#define MAXET (MAXN + MAXE)
#define NGR 32

// ---------------- device scratch (no allocs allowed) ----------------
__device__ float g_h768[MAXN * 768];
__device__ float g_T[(size_t)MAXN * 1024];
__device__ float g_G[(size_t)MAXN * 1024];
__device__ float g_x1[(size_t)MAXN * 1024];
__device__ float g_x2[(size_t)MAXN * 1024];
__device__ float g_x3[MAXN * 256];
__device__ float g_es[MAXN * 4];
__device__ float g_ed[MAXN * 4];
__device__ int   g_deg[MAXN];
__device__ int   g_off[MAXN + 1];
__device__ int   g_cur[MAXN];
__device__ int   g_csr[MAXET];
__device__ int   g_csrd[MAXET];
__device__ float g_hmax[MAXN * 4];
__device__ float g_hden[MAXN * 4];
__device__ float g_alphae[(size_t)MAXET * 4];
__device__ float g_psum[NGR * 4 * 256];
__device__ float g_pmax[NGR * 4 * 256];
__device__ int   g_pcnt[NGR * 4];

// packed bf16x2 hi/lo buffers (pre-split once per layer)
__device__ unsigned g_pa_h[(size_t)MAXN * 512];   // A packed: [m][kpair], KP<=512
__device__ unsigned g_pa_l[(size_t)MAXN * 512];
__device__ unsigned g_pw_h[1024 * 512];           // W packed: [n][kpair], N<=1024
__device__ unsigned g_pw_l[1024 * 512];

#define BUF_H768 0
#define BUF_T    1
#define BUF_G    2
#define BUF_X1   3
#define BUF_X2   4
#define BUF_X3   5
__device__ float* const g_fptr[6] = { g_h768, g_T, g_G, g_x1, g_x2, g_x3 };

// ---------------- helpers ----------------
__device__ __forceinline__ float atomicMaxF(float* addr, float value) {
    if (value >= 0.f)
        return __int_as_float(atomicMax((int*)addr, __float_as_int(value)));
    else
        return __uint_as_float(atomicMin((unsigned int*)addr, __float_as_uint(value)));
}

__device__ __forceinline__ void bf_split(float x, unsigned short& hi, unsigned short& lo) {
    __nv_bfloat16 h = __float2bfloat16_rn(x);
    float hf = __bfloat162float(h);
    __nv_bfloat16 l = __float2bfloat16_rn(x - hf);
    hi = __bfloat16_as_ushort(h);
    lo = __bfloat16_as_ushort(l);
}

__device__ __forceinline__ void mma_bf16(float c[4], unsigned a0, unsigned a1, unsigned a2, unsigned a3,
                                         unsigned b0, unsigned b1) {
    asm volatile(
        "mma.sync.aligned.m16n8k16.row.col.f32.bf16.bf16.f32 "
        "{%0,%1,%2,%3}, {%4,%5,%6,%7}, {%8,%9}, {%0,%1,%2,%3};"
        : "+f"(c[0]), "+f"(c[1]), "+f"(c[2]), "+f"(c[3])
        : "r"(a0), "r"(a1), "r"(a2), "r"(a3), "r"(b0), "r"(b1));
}

__device__ __forceinline__ void cp16(unsigned dst_smem, const void* src, int src_size) {
    asm volatile("cp.async.cg.shared.global [%0], [%1], 16, %2;"
                 :: "r"(dst_smem), "l"(src), "r"(src_size));
}

// ---------------- CSR build ----------------
__global__ void k_zero_deg(int n) {
    int i = blockIdx.x * 256 + threadIdx.x;
    if (i < n) g_deg[i] = 0;
}

__global__ void k_count_deg(const int* __restrict__ ei, int E, int N) {
    int i = blockIdx.x * 256 + threadIdx.x;
    if (i >= E + N) return;
    int dst = (i < E) ? ei[E + i] : (i - E);
    atomicAdd(&g_deg[dst], 1);
}

__global__ void __launch_bounds__(1024) k_scan_deg(int n) {
    const int NT = 1024;
    int tid = threadIdx.x;
    int chunk = (n + NT - 1) / NT;
    int b0 = tid * chunk;
    int lsum = 0;
    for (int i = 0; i < chunk; i++) {
        int j = b0 + i;
        if (j < n) lsum += g_deg[j];
    }
    __shared__ int s[NT];
    s[tid] = lsum;
    __syncthreads();
    for (int o = 1; o < NT; o <<= 1) {
        int t = (tid >= o) ? s[tid - o] : 0;
        __syncthreads();
        s[tid] += t;
        __syncthreads();
    }
    int run = s[tid] - lsum;
    for (int i = 0; i < chunk; i++) {
        int j = b0 + i;
        if (j < n) { g_off[j] = run; g_cur[j] = run; run += g_deg[j]; }
    }
    if (tid == NT - 1) g_off[n] = s[NT - 1];
}

__global__ void k_scatter_edges(const int* __restrict__ ei, int E, int N) {
    int i = blockIdx.x * 256 + threadIdx.x;
    if (i >= E + N) return;
    int src, dst;
    if (i < E) { src = ei[i]; dst = ei[E + i]; }
    else       { src = i - E; dst = i - E; }
    int pos = atomicAdd(&g_cur[dst], 1);
    g_csr[pos] = src;
    g_csrd[pos] = dst;
}

// ---------------- pack kernels: fp32 -> bf16 hi/lo packed pairs ----------------
__global__ void k_packA(const float* __restrict__ Aext, int a_id, int MKP) {
    const float* __restrict__ A = Aext ? Aext : g_fptr[a_id];
    int i = blockIdx.x * 256 + threadIdx.x;
    if (i >= MKP) return;
    float2 v = *(const float2*)(A + (size_t)i * 2);
    unsigned short h0, l0, h1, l1;
    bf_split(v.x, h0, l0);
    bf_split(v.y, h1, l1);
    g_pa_h[i] = (unsigned)h0 | ((unsigned)h1 << 16);
    g_pa_l[i] = (unsigned)l0 | ((unsigned)l1 << 16);
}

__global__ void k_packW(const float* __restrict__ W, int N, int KP) {
    int u = blockIdx.x * 256 + threadIdx.x;
    if (u >= N * KP) return;
    int kp = u / N, n = u - kp * N;
    float a = W[(size_t)(2 * kp) * N + n];
    float b = W[(size_t)(2 * kp + 1) * N + n];
    unsigned short ha, la, hb, lb;
    bf_split(a, ha, la);
    bf_split(b, hb, lb);
    g_pw_h[(size_t)n * KP + kp] = (unsigned)ha | ((unsigned)hb << 16);
    g_pw_l[(size_t)n * KP + kp] = (unsigned)la | ((unsigned)lb << 16);
}

// ---------------- Tensor-core GEMM (pre-packed bf16 hi/lo, 3 terms, cp.async 2-stage) ----
#define GM 128
#define GN 128
#define SLD 20
template <int ACT>
__global__ void __launch_bounds__(256) k_tgemm(const float* __restrict__ bias, int c_id,
                                               int M, int N, int K) {
    float* __restrict__ C = g_fptr[c_id];
    const int KP = K >> 1;

    __shared__ __align__(16) unsigned SB[2][4][GM][SLD];

    int tid = threadIdx.x, wid = tid >> 5, lane = tid & 31;
    int warp_m = wid & 1, warp_n = wid >> 1;
    int row0 = blockIdx.y * GM, col0 = blockIdx.x * GN;
    int qr = lane >> 2, qc = lane & 3;

    float acc[4][4][4] = {};

    const int r_ld = tid >> 1;
    const int c4_ld = (tid & 1) * 8;
    const int gr = row0 + r_ld;
    const int asz = (gr < M) ? 16 : 0;
    const int gra = (gr < M) ? gr : (M - 1);
    const int wrow = col0 + r_ld;

    const int NTILES = KP >> 4;

    auto load_tile = [&](int t, int st) {
        int kp0 = t << 4;
        const unsigned* pah = &g_pa_h[(size_t)gra * KP + kp0 + c4_ld];
        const unsigned* pal = &g_pa_l[(size_t)gra * KP + kp0 + c4_ld];
        cp16((unsigned)__cvta_generic_to_shared(&SB[st][0][r_ld][c4_ld]), pah, asz);
        cp16((unsigned)__cvta_generic_to_shared(&SB[st][0][r_ld][c4_ld + 4]), pah + 4, asz);
        cp16((unsigned)__cvta_generic_to_shared(&SB[st][1][r_ld][c4_ld]), pal, asz);
        cp16((unsigned)__cvta_generic_to_shared(&SB[st][1][r_ld][c4_ld + 4]), pal + 4, asz);
        const unsigned* pwh = &g_pw_h[(size_t)wrow * KP + kp0 + c4_ld];
        const unsigned* pwl = &g_pw_l[(size_t)wrow * KP + kp0 + c4_ld];
        cp16((unsigned)__cvta_generic_to_shared(&SB[st][2][r_ld][c4_ld]), pwh, 16);
        cp16((unsigned)__cvta_generic_to_shared(&SB[st][2][r_ld][c4_ld + 4]), pwh + 4, 16);
        cp16((unsigned)__cvta_generic_to_shared(&SB[st][3][r_ld][c4_ld]), pwl, 16);
        cp16((unsigned)__cvta_generic_to_shared(&SB[st][3][r_ld][c4_ld + 4]), pwl + 4, 16);
    };

    load_tile(0, 0);
    asm volatile("cp.async.commit_group;");

    for (int t = 0; t < NTILES; t++) {
        int p = t & 1;
        if (t + 1 < NTILES) load_tile(t + 1, p ^ 1);
        asm volatile("cp.async.commit_group;");
        asm volatile("cp.async.wait_group 1;");
        __syncthreads();

        unsigned (*Ah)[SLD] = SB[p][0];
        unsigned (*Al)[SLD] = SB[p][1];
        unsigned (*Wh)[SLD] = SB[p][2];
        unsigned (*Wl)[SLD] = SB[p][3];

#pragma unroll
        for (int kk = 0; kk < 2; kk++) {
            int kb = kk * 8;
            unsigned ah[4][4], al[4][4];
#pragma unroll
            for (int i = 0; i < 4; i++) {
                int r = warp_m * 64 + i * 16;
                ah[i][0] = Ah[r + qr][kb + qc];
                ah[i][1] = Ah[r + qr + 8][kb + qc];
                ah[i][2] = Ah[r + qr][kb + qc + 4];
                ah[i][3] = Ah[r + qr + 8][kb + qc + 4];
                al[i][0] = Al[r + qr][kb + qc];
                al[i][1] = Al[r + qr + 8][kb + qc];
                al[i][2] = Al[r + qr][kb + qc + 4];
                al[i][3] = Al[r + qr + 8][kb + qc + 4];
            }
            unsigned bh[4][2], bl[4][2];
#pragma unroll
            for (int j = 0; j < 4; j++) {
                int c = warp_n * 32 + j * 8 + qr;
                bh[j][0] = Wh[c][kb + qc];
                bh[j][1] = Wh[c][kb + qc + 4];
                bl[j][0] = Wl[c][kb + qc];
                bl[j][1] = Wl[c][kb + qc + 4];
            }
#pragma unroll
            for (int i = 0; i < 4; i++)
#pragma unroll
                for (int j = 0; j < 4; j++) {
                    mma_bf16(acc[i][j], ah[i][0], ah[i][1], ah[i][2], ah[i][3], bh[j][0], bh[j][1]);
                    mma_bf16(acc[i][j], al[i][0], al[i][1], al[i][2], al[i][3], bh[j][0], bh[j][1]);
                    mma_bf16(acc[i][j], ah[i][0], ah[i][1], ah[i][2], ah[i][3], bl[j][0], bl[j][1]);
                }
        }
        __syncthreads();
    }

#pragma unroll
    for (int i = 0; i < 4; i++) {
#pragma unroll
        for (int j = 0; j < 4; j++) {
            int rg = row0 + warp_m * 64 + i * 16 + qr;
            int cg = col0 + warp_n * 32 + j * 8 + qc * 2;
            float b0v = 0.f, b1v = 0.f;
            if (bias) { b0v = bias[cg]; b1v = bias[cg + 1]; }
#pragma unroll
            for (int half = 0; half < 2; half++) {
                int r = rg + half * 8;
                if (r >= M) continue;
                float vx = acc[i][j][half * 2 + 0] + b0v;
                float vy = acc[i][j][half * 2 + 1] + b1v;
                if (ACT == 1) {
                    vx = vx > 0.f ? vx : (expf(vx) - 1.0f);
                    vy = vy > 0.f ? vy : (expf(vy) - 1.0f);
                }
                float2 v2 = make_float2(vx, vy);
                *(float2*)(C + (size_t)r * N + cg) = v2;
            }
        }
    }
}

// ---------------- attention dot products ----------------
__global__ void k_att_dots(const float* __restrict__ as_, const float* __restrict__ ad_,
                           int NH, int H, int C) {
    const float* __restrict__ T = g_T;
    int gw = (blockIdx.x * blockDim.x + threadIdx.x) >> 5;
    int lane = threadIdx.x & 31;
    if (gw >= NH) return;
    int n = gw / H, h = gw - n * H;
    const float* row = T + (size_t)n * H * C + (size_t)h * C;
    float a = 0.f, d = 0.f;
    for (int c = lane; c < C; c += 32) {
        float v = row[c];
        a += v * as_[h * C + c];
        d += v * ad_[h * C + c];
    }
    for (int o = 16; o; o >>= 1) {
        a += __shfl_xor_sync(0xffffffffu, a, o);
        d += __shfl_xor_sync(0xffffffffu, d, o);
    }
    if (lane == 0) { g_es[gw] = a; g_ed[gw] = d; }
}

// ---------------- edge-parallel softmax precompute ----------------
__global__ void k_att_init(int NH) {
    int i = blockIdx.x * 256 + threadIdx.x;
    if (i < NH) { g_hmax[i] = -INFINITY; g_hden[i] = 0.f; }
}

template <int H>
__global__ void k_edge_max(int ET) {
    int e = blockIdx.x * 256 + threadIdx.x;
    if (e >= ET) return;
    int src = g_csr[e], dst = g_csrd[e];
#pragma unroll
    for (int h = 0; h < H; h++) {
        float l = g_es[src * H + h] + g_ed[dst * H + h];
        l = l > 0.f ? l : 0.2f * l;
        atomicMaxF(&g_hmax[dst * H + h], l);
    }
}

template <int H>
__global__ void k_edge_ex(int ET) {
    int e = blockIdx.x * 256 + threadIdx.x;
    if (e >= ET) return;
    int src = g_csr[e], dst = g_csrd[e];
    float ex[H];
#pragma unroll
    for (int h = 0; h < H; h++) {
        float l = g_es[src * H + h] + g_ed[dst * H + h];
        l = l > 0.f ? l : 0.2f * l;
        ex[h] = expf(l - g_hmax[dst * H + h]);
        atomicAdd(&g_hden[dst * H + h], ex[h]);
    }
    if (H == 4) {
        float4 v = make_float4(ex[0], ex[1], ex[2], ex[3]);
        *(float4*)(g_alphae + (size_t)e * 4) = v;
    } else {
        g_alphae[e] = ex[0];
    }
}

// ---------------- GAT aggregation (gather only; softmax precomputed) ----------------
template <int H, int CPT>
__global__ void __launch_bounds__(256) k_gat_agg(const float* __restrict__ bias) {
    const int F = 256 * CPT;
    const float* __restrict__ T = g_T;
    float* __restrict__ out = g_G;
    int node = blockIdx.x;
    int tid = threadIdx.x;
    int beg = g_off[node], end = g_off[node + 1];

    float inv[H];
#pragma unroll
    for (int h = 0; h < H; h++) inv[h] = 1.0f / (g_hden[node * H + h] + 1e-16f);

    float acc[CPT] = {};
    __shared__ int s_src[256];
    __shared__ float s_alpha[256 * H];
    for (int cbk = beg; cbk < end; cbk += 256) {
        int cn = min(256, end - cbk);
        if (tid < cn) {
            s_src[tid] = g_csr[cbk + tid];
            if (H == 4) {
                float4 ex4 = *(const float4*)(g_alphae + (size_t)(cbk + tid) * 4);
                s_alpha[tid * 4 + 0] = ex4.x * inv[0];
                s_alpha[tid * 4 + 1] = ex4.y * inv[1];
                s_alpha[tid * 4 + 2] = ex4.z * inv[2];
                s_alpha[tid * 4 + 3] = ex4.w * inv[3];
            } else {
                s_alpha[tid] = g_alphae[cbk + tid] * inv[0];
            }
        }
        __syncthreads();
        if (CPT == 4) {
            const int head = tid >> 6;
            int j = 0;
            for (; j + 4 <= cn; j += 4) {
                int s0 = s_src[j], s1 = s_src[j + 1], s2 = s_src[j + 2], s3 = s_src[j + 3];
                float a0 = s_alpha[(j + 0) * 4 + head];
                float a1 = s_alpha[(j + 1) * 4 + head];
                float a2 = s_alpha[(j + 2) * 4 + head];
                float a3 = s_alpha[(j + 3) * 4 + head];
                float4 v0 = *(const float4*)(T + (size_t)s0 * F + tid * 4);
                float4 v1 = *(const float4*)(T + (size_t)s1 * F + tid * 4);
                float4 v2 = *(const float4*)(T + (size_t)s2 * F + tid * 4);
                float4 v3 = *(const float4*)(T + (size_t)s3 * F + tid * 4);
                acc[0] += a0 * v0.x + a1 * v1.x + a2 * v2.x + a3 * v3.x;
                acc[1] += a0 * v0.y + a1 * v1.y + a2 * v2.y + a3 * v3.y;
                acc[2] += a0 * v0.z + a1 * v1.z + a2 * v2.z + a3 * v3.z;
                acc[3] += a0 * v0.w + a1 * v1.w + a2 * v2.w + a3 * v3.w;
            }
            for (; j < cn; j++) {
                int s = s_src[j];
                float alpha = s_alpha[j * 4 + head];
                float4 v = *(const float4*)(T + (size_t)s * F + tid * 4);
                acc[0] += alpha * v.x;
                acc[1] += alpha * v.y;
                acc[2] += alpha * v.z;
                acc[3] += alpha * v.w;
            }
        } else {
            int j = 0;
            for (; j + 4 <= cn; j += 4) {
                int s0 = s_src[j], s1 = s_src[j + 1], s2 = s_src[j + 2], s3 = s_src[j + 3];
                float a0 = s_alpha[j], a1 = s_alpha[j + 1], a2 = s_alpha[j + 2], a3 = s_alpha[j + 3];
                float v0 = T[(size_t)s0 * F + tid];
                float v1 = T[(size_t)s1 * F + tid];
                float v2 = T[(size_t)s2 * F + tid];
                float v3 = T[(size_t)s3 * F + tid];
                acc[0] += a0 * v0 + a1 * v1 + a2 * v2 + a3 * v3;
            }
            for (; j < cn; j++) {
                int s = s_src[j];
                acc[0] += s_alpha[j] * T[(size_t)s * F + tid];
            }
        }
        __syncthreads();
    }
#pragma unroll
    for (int q = 0; q < CPT; q++) {
        int c = tid * CPT + q;
        out[(size_t)node * F + c] = acc[q] + bias[c];
    }
}

// ---------------- LayerNorm + ELU (+ optional residual added AFTER elu) ----------------
__global__ void __launch_bounds__(256) k_ln_elu(const float* __restrict__ g,
                                                const float* __restrict__ b,
                                                int res_id, int out_id, int F) {
    const float* __restrict__ in = g_G;
    const float* __restrict__ res = (res_id >= 0) ? g_fptr[res_id] : nullptr;
    float* __restrict__ out = g_fptr[out_id];
    int node = blockIdx.x, tid = threadIdx.x;
    const float* row = in + (size_t)node * F;
    int nv = F >> 2;
    float s = 0.f, s2 = 0.f;
    for (int q = tid; q < nv; q += 256) {
        float4 v = *(const float4*)(row + q * 4);
        s += v.x + v.y + v.z + v.w;
        s2 += v.x * v.x + v.y * v.y + v.z * v.z + v.w * v.w;
    }
    __shared__ float sh[8], sh2[8];
    for (int o = 16; o; o >>= 1) {
        s += __shfl_xor_sync(0xffffffffu, s, o);
        s2 += __shfl_xor_sync(0xffffffffu, s2, o);
    }
    if ((tid & 31) == 0) { sh[tid >> 5] = s; sh2[tid >> 5] = s2; }
    __syncthreads();
    __shared__ float smean, sinv;
    if (tid == 0) {
        float ts = 0.f, t2 = 0.f;
        for (int w = 0; w < 8; w++) { ts += sh[w]; t2 += sh2[w]; }
        float mean = ts / F;
        float var = t2 / F - mean * mean;
        if (var < 0.f) var = 0.f;
        smean = mean;
        sinv = rsqrtf(var + 1e-5f);
    }
    __syncthreads();
    float mean = smean, inv = sinv;
    for (int q = tid; q < nv; q += 256) {
        int c = q * 4;
        float4 v = *(const float4*)(row + c);
        float4 gg = *(const float4*)(g + c);
        float4 bb = *(const float4*)(b + c);
        v.x = (v.x - mean) * inv * gg.x + bb.x;
        v.y = (v.y - mean) * inv * gg.y + bb.y;
        v.z = (v.z - mean) * inv * gg.z + bb.z;
        v.w = (v.w - mean) * inv * gg.w + bb.w;
        v.x = v.x > 0.f ? v.x : (expf(v.x) - 1.0f);
        v.y = v.y > 0.f ? v.y : (expf(v.y) - 1.0f);
        v.z = v.z > 0.f ? v.z : (expf(v.z) - 1.0f);
        v.w = v.w > 0.f ? v.w : (expf(v.w) - 1.0f);
        if (res) {
            float4 rr = *(const float4*)(res + (size_t)node * F + c);
            v.x += rr.x; v.y += rr.y; v.z += rr.z; v.w += rr.w;
        }
        *(float4*)(out + (size_t)node * F + c) = v;
    }
}

// ---------------- pooling: deterministic per-graph (batch is sorted) ----------------
__global__ void __launch_bounds__(256) k_pool_graph(const int* __restrict__ batch, int N) {
    int gph = blockIdx.x, q = blockIdx.y;
    int tid = threadIdx.x;
    // binary search [lo, hi) with batch == gph
    int lo = 0, hi = N;
    {
        int a = 0, b = N;
        while (a < b) { int m = (a + b) >> 1; if (batch[m] < gph) a = m + 1; else b = m; }
        lo = a;
        a = lo; b = N;
        while (a < b) { int m = (a + b) >> 1; if (batch[m] < gph + 1) a = m + 1; else b = m; }
        hi = a;
    }
    int cnt = hi - lo;
    int qlen = (cnt + 3) >> 2;
    int s = lo + q * qlen;
    int e2 = min(hi, s + qlen);
    float sum = 0.f, mx = -INFINITY;
    for (int n = s; n < e2; n++) {
        float v = g_x3[(size_t)n * 256 + tid];
        sum += v;
        mx = fmaxf(mx, v);
    }
    int slot = gph * 4 + q;
    g_psum[slot * 256 + tid] = sum;
    g_pmax[slot * 256 + tid] = mx;
    if (tid == 0) g_pcnt[slot] = (e2 > s) ? (e2 - s) : 0;
}

// ---------------- classifier head ----------------
__global__ void __launch_bounds__(128) k_classify(const float* __restrict__ w1, const float* __restrict__ b1,
                                                  const float* __restrict__ w2, const float* __restrict__ b2,
                                                  float* __restrict__ out) {
    int gph = blockIdx.x, tid = threadIdx.x;
    __shared__ float p[768];
    int cnt = g_pcnt[gph * 4] + g_pcnt[gph * 4 + 1] + g_pcnt[gph * 4 + 2] + g_pcnt[gph * 4 + 3];
    float fcnt = (float)max(cnt, 1);
    for (int j = tid; j < 256; j += 128) {
        float sm = 0.f, mx = -INFINITY;
#pragma unroll
        for (int q = 0; q < 4; q++) {
            sm += g_psum[(gph * 4 + q) * 256 + j];
            mx = fmaxf(mx, g_pmax[(gph * 4 + q) * 256 + j]);
        }
        p[j] = sm / fcnt;
        p[256 + j] = mx;
        p[512 + j] = sm;
    }
    __syncthreads();
    float h = b1[tid];
    for (int j = 0; j < 768; j++) h += p[j] * w1[j * 128 + tid];
    h = h > 0.f ? h : 0.f;
    float part = h * w2[tid];
    for (int o = 16; o; o >>= 1) part += __shfl_xor_sync(0xffffffffu, part, o);
    __shared__ float sr[4];
    if ((tid & 31) == 0) sr[tid >> 5] = part;
    __syncthreads();
    if (tid == 0) out[gph] = sr[0] + sr[1] + sr[2] + sr[3] + b2[0];
}

// ---------------- launch (pure kernel launches; graph-capture safe) ----------------
extern "C" void kernel_launch(void* const* d_in, const int* in_sizes, int n_in,
                              void* d_out, int out_size) {
    const float* x = (const float*)d_in[0];
    const int* ei = (const int*)d_in[1];
    const int* batch = (const int*)d_in[2];
    const float* proj_w = (const float*)d_in[3];
    const float* proj_b = (const float*)d_in[4];
    const float* gat1_w = (const float*)d_in[5];
    const float* att1_src = (const float*)d_in[6];
    const float* att1_dst = (const float*)d_in[7];
    const float* gat1_b = (const float*)d_in[8];
    const float* ln1_g = (const float*)d_in[9];
    const float* ln1_b = (const float*)d_in[10];
    const float* gat2_w = (const float*)d_in[11];
    const float* att2_src = (const float*)d_in[12];
    const float* att2_dst = (const float*)d_in[13];
    const float* gat2_b = (const float*)d_in[14];
    const float* ln2_g = (const float*)d_in[15];
    const float* ln2_b = (const float*)d_in[16];
    const float* gat3_w = (const float*)d_in[17];
    const float* att3_src = (const float*)d_in[18];
    const float* att3_dst = (const float*)d_in[19];
    const float* gat3_b = (const float*)d_in[20];
    const float* ln3_g = (const float*)d_in[21];
    const float* ln3_b = (const float*)d_in[22];
    const float* cls1_w = (const float*)d_in[23];
    const float* cls1_b = (const float*)d_in[24];
    const float* cls2_w = (const float*)d_in[25];
    const float* cls2_b = (const float*)d_in[26];
    float* out = (float*)d_out;

    int N = in_sizes[0] / 768;
    int E = in_sizes[1] / 2;
    int ET = E + N;

    dim3 thr(256);
    int mgrid = (N + GM - 1) / GM;
    int mkp384 = N * 384, mkp512 = N * 512;
    int egrid = (ET + 255) / 256;

    // ---- proj layer first; CSR build interleaved so launch #4 = k_tgemm (ncu) ----
    k_packW<<<(768 * 384 + 255) / 256, thr>>>(proj_w, 768, 384);
    k_packA<<<(mkp384 + 255) / 256, thr>>>(x, 0, mkp384);
    k_zero_deg<<<(N + 255) / 256, 256>>>(N);
    k_tgemm<1><<<dim3(768 / GN, mgrid), thr>>>(proj_b, BUF_H768, N, 768, 768);
    k_count_deg<<<(ET + 255) / 256, 256>>>(ei, E, N);
    k_scan_deg<<<1, 1024>>>(N);
    k_scatter_edges<<<(ET + 255) / 256, 256>>>(ei, E, N);

    // ---- GAT layer 1: 768 -> 4x256 concat ----
    k_packW<<<(1024 * 384 + 255) / 256, thr>>>(gat1_w, 1024, 384);
    k_packA<<<(mkp384 + 255) / 256, thr>>>(nullptr, BUF_H768, mkp384);
    k_tgemm<0><<<dim3(1024 / GN, mgrid), thr>>>(nullptr, BUF_T, N, 1024, 768);
    k_att_dots<<<(N * 4 * 32 + 255) / 256, 256>>>(att1_src, att1_dst, N * 4, 4, 256);
    k_att_init<<<(N * 4 + 255) / 256, 256>>>(N * 4);
    k_edge_max<4><<<egrid, 256>>>(ET);
    k_edge_ex<4><<<egrid, 256>>>(ET);
    k_gat_agg<4, 4><<<N, 256>>>(gat1_b);
    k_ln_elu<<<N, 256>>>(ln1_g, ln1_b, -1, BUF_X1, 1024);

    // ---- GAT layer 2: 1024 -> 4x256 concat, residual ----
    k_packW<<<(1024 * 512 + 255) / 256, thr>>>(gat2_w, 1024, 512);
    k_packA<<<(mkp512 + 255) / 256, thr>>>(nullptr, BUF_X1, mkp512);
    k_tgemm<0><<<dim3(1024 / GN, mgrid), thr>>>(nullptr, BUF_T, N, 1024, 1024);
    k_att_dots<<<(N * 4 * 32 + 255) / 256, 256>>>(att2_src, att2_dst, N * 4, 4, 256);
    k_att_init<<<(N * 4 + 255) / 256, 256>>>(N * 4);
    k_edge_max<4><<<egrid, 256>>>(ET);
    k_edge_ex<4><<<egrid, 256>>>(ET);
    k_gat_agg<4, 4><<<N, 256>>>(gat2_b);
    k_ln_elu<<<N, 256>>>(ln2_g, ln2_b, BUF_X1, BUF_X2, 1024);

    // ---- GAT layer 3: 1024 -> 1x256 ----
    k_packW<<<(256 * 512 + 255) / 256, thr>>>(gat3_w, 256, 512);
    k_packA<<<(mkp512 + 255) / 256, thr>>>(nullptr, BUF_X2, mkp512);
    k_tgemm<0><<<dim3(256 / GN, mgrid), thr>>>(nullptr, BUF_T, N, 256, 1024);
    k_att_dots<<<(N * 1 * 32 + 255) / 256, 256>>>(att3_src, att3_dst, N * 1, 1, 256);
    k_att_init<<<(N * 1 + 255) / 256, 256>>>(N * 1);
    k_edge_max<1><<<egrid, 256>>>(ET);
    k_edge_ex<1><<<egrid, 256>>>(ET);
    k_gat_agg<1, 1><<<N, 256>>>(gat3_b);
    k_ln_elu<<<N, 256>>>(ln3_g, ln3_b, -1, BUF_X3, 256);

    // ---- pooling + classifier (deterministic, atomic-free) ----
    k_pool_graph<<<dim3(NGR, 4), 256>>>(batch, N);
    k_classify<<<NGR, 128>>>(cls1_w, cls1_b, cls2_w, cls2_b, out);
}